// round 8
// baseline (speedup 1.0000x reference)
#include <cuda_runtime.h>
#include <cuda_bf16.h>
#include <math.h>
#include <stdint.h>

#define NH 8
#define GROW 512            // gmem row stride (NH*HD)
#define OUT_ELEMS 2097152   // 4*1024*8*64
#define QB_OFF 0            // Q packed bf16 hi/lo: 64 units * 528B
#define KB_OFF 33792        // K packed bf16 hi/lo: 64 keys * 320B (image copy)
#define VP_OFF 54272        // V packed tf32: 64 d * 288B (image copy)
#define PP_OFF 72704        // P packed tf32: 64 units * 544B
#define LP_OFF 107520       // row-sum partials: 2 * 128 floats
#define SMEM_TOTAL 108544
#define KIMG_F4 1280        // 20480B / 16
#define VIMG_F4 1152        // 18432B / 16

__device__ float4 g_kimg[NH * 64 * KIMG_F4];   // packed K tile images
__device__ float4 g_vimg[NH * 64 * VIMG_F4];   // packed V tile images
__device__ float g_scrO[512 * 8192];           // partial O
__device__ float g_scrL[512 * 128];            // partial l
__device__ int   g_flags[256];                 // per-tile arrival counters (self-resetting)

__device__ __forceinline__ float tf32_rna(float x) {
    float y; asm("cvt.rna.tf32.f32 %0, %1;" : "=f"(y) : "f"(x)); return y;
}
__device__ __forceinline__ void mma_bf16(float4& c,
    uint32_t a0, uint32_t a1, uint32_t a2, uint32_t a3, uint32_t b0, uint32_t b1)
{
    asm volatile(
        "mma.sync.aligned.m16n8k16.row.col.f32.bf16.bf16.f32 "
        "{%0,%1,%2,%3}, {%4,%5,%6,%7}, {%8,%9}, {%0,%1,%2,%3};\n"
        : "+f"(c.x), "+f"(c.y), "+f"(c.z), "+f"(c.w)
        : "r"(a0), "r"(a1), "r"(a2), "r"(a3), "r"(b0), "r"(b1));
}
__device__ __forceinline__ void mma_tf32(float4& c,
    float a0, float a1, float a2, float a3, float b0, float b1)
{
    asm volatile(
        "mma.sync.aligned.m16n8k8.row.col.f32.tf32.tf32.f32 "
        "{%0,%1,%2,%3}, {%4,%5,%6,%7}, {%8,%9}, {%0,%1,%2,%3};\n"
        : "+f"(c.x), "+f"(c.y), "+f"(c.z), "+f"(c.w)
        : "r"(__float_as_uint(a0)), "r"(__float_as_uint(a1)),
          "r"(__float_as_uint(a2)), "r"(__float_as_uint(a3)),
          "r"(__float_as_uint(b0)), "r"(__float_as_uint(b1)));
}
__device__ __forceinline__ uint32_t pack2(float a, float b) {
    __nv_bfloat162 t = __floats2bfloat162_rn(a, b);
    return *reinterpret_cast<uint32_t*>(&t);
}
__device__ __forceinline__ uint32_t smem_u32(const void* p) {
    uint32_t a;
    asm("{ .reg .u64 t; cvta.to.shared.u64 t, %1; cvt.u32.u64 %0, t; }" : "=r"(a) : "l"(p));
    return a;
}
__device__ __forceinline__ void cp16(uint32_t saddr, const void* g) {
    asm volatile("cp.async.cg.shared.global [%0], [%1], 16;" :: "r"(saddr), "l"(g) : "memory");
}
#define CP_COMMIT() asm volatile("cp.async.commit_group;" ::: "memory")
#define CP_WAIT1()  asm volatile("cp.async.wait_group 1;" ::: "memory")

// ---- prep: pack K/V tiles into gmem images (exact smem byte layout) ----
__global__ __launch_bounds__(256) void zz_prep(
    const float* __restrict__ k, const float* __restrict__ v)
{
    extern __shared__ char sm[];
    const int tid = threadIdx.x;
    const int jt = blockIdx.x, h = blockIdx.y;
#pragma unroll
    for (int it = 0; it < 4; it++) {
        int idx = tid + it * 256;
        int key = idx >> 4, d4 = (idx & 15) << 2;
        int goff = (jt * 64 + key) * GROW + h * 64 + d4;
        float4 kv = *reinterpret_cast<const float4*>(&k[goff]);
        float4 vv = *reinterpret_cast<const float4*>(&v[goff]);
        __nv_bfloat162 h01 = __floats2bfloat162_rn(kv.x, kv.y);
        __nv_bfloat162 h23 = __floats2bfloat162_rn(kv.z, kv.w);
        uint32_t hi01 = *reinterpret_cast<uint32_t*>(&h01);
        uint32_t hi23 = *reinterpret_cast<uint32_t*>(&h23);
        uint32_t lo01 = pack2(kv.x - __bfloat162float(h01.x), kv.y - __bfloat162float(h01.y));
        uint32_t lo23 = pack2(kv.z - __bfloat162float(h23.x), kv.w - __bfloat162float(h23.y));
        int kt = d4 >> 4, dp = d4 & 15, hf = dp >> 3, qd0 = (dp & 7) >> 1;
        char* kb_ = sm + key * 320 + kt * 64;
        *reinterpret_cast<uint32_t*>(kb_ + qd0 * 16 + hf * 4) = hi01;
        *reinterpret_cast<uint32_t*>(kb_ + (qd0 + 1) * 16 + hf * 4) = hi23;
        *reinterpret_cast<uint32_t*>(kb_ + qd0 * 16 + 8 + hf * 4) = lo01;
        *reinterpret_cast<uint32_t*>(kb_ + (qd0 + 1) * 16 + 8 + hf * 4) = lo23;
        int kc = key >> 3, qv_ = key & 3, sel = (key >> 2) & 1;
        char* vb = sm + 20480 + kc * 32 + qv_ * 8 + sel * 4;
        *reinterpret_cast<float*>(vb + (d4 + 0) * 288) = tf32_rna(vv.x);
        *reinterpret_cast<float*>(vb + (d4 + 1) * 288) = tf32_rna(vv.y);
        *reinterpret_cast<float*>(vb + (d4 + 2) * 288) = tf32_rna(vv.z);
        *reinterpret_cast<float*>(vb + (d4 + 3) * 288) = tf32_rna(vv.w);
    }
    __syncthreads();
    float4* dstK = g_kimg + (h * 64 + jt) * KIMG_F4;
    const float4* srcK = reinterpret_cast<const float4*>(sm);
#pragma unroll
    for (int i = tid; i < KIMG_F4; i += 256) dstK[i] = srcK[i];
    float4* dstV = g_vimg + (h * 64 + jt) * VIMG_F4;
    const float4* srcV = reinterpret_cast<const float4*>(sm + 20480);
#pragma unroll
    for (int i = tid; i < VIMG_F4; i += 256) dstV[i] = srcV[i];
}

__global__ __launch_bounds__(256, 2) void zz_fa_part(
    const float* __restrict__ q, float* __restrict__ out)
{
    extern __shared__ char sm[];
    __shared__ int s_old;
    __shared__ float inv_s[128];
    __shared__ float lse_s[128];
    const uint32_t sb = smem_u32(sm);
    const int tid = threadIdx.x;
    const int w = tid >> 5, lane = tid & 31, grp = lane >> 2, qd = lane & 3;
    const int rslot = w >> 1, ch = w & 1;
    const int bx = blockIdx.x;
    const int qb = 31 - (bx >> 4);        // heavy q-tiles first
    const int h = (bx >> 1) & 7;
    const int half = bx & 1;
    const int qbase = qb * 128;

    // ---- pack Q once (scale * log2e folded in, bf16 hi/lo split) ----
    const float qscale = 0.125f * 1.4426950408889634f;
    for (int idx = tid; idx < 2048; idx += 256) {
        int row = idx >> 4, d4 = (idx & 15) << 2;
        float4 qv = *reinterpret_cast<const float4*>(&q[(qbase + row) * GROW + h * 64 + d4]);
        float f0 = qv.x * qscale, f1 = qv.y * qscale, f2 = qv.z * qscale, f3 = qv.w * qscale;
        __nv_bfloat162 h01 = __floats2bfloat162_rn(f0, f1);
        __nv_bfloat162 h23 = __floats2bfloat162_rn(f2, f3);
        uint32_t hi01 = *reinterpret_cast<uint32_t*>(&h01);
        uint32_t hi23 = *reinterpret_cast<uint32_t*>(&h23);
        uint32_t lo01 = pack2(f0 - __bfloat162float(h01.x), f1 - __bfloat162float(h01.y));
        uint32_t lo23 = pack2(f2 - __bfloat162float(h23.x), f3 - __bfloat162float(h23.y));
        int mt = row >> 4, g = row & 7, rh = (row >> 3) & 1;
        int kt = d4 >> 4, dp = d4 & 15, hf = dp >> 3, qd0 = (dp & 7) >> 1;
        int comp = hf * 2 + rh;
        char* ub = sm + QB_OFF + (mt * 8 + g) * 528 + kt * 128;
        *reinterpret_cast<uint32_t*>(ub + qd0 * 32 + comp * 4) = hi01;
        *reinterpret_cast<uint32_t*>(ub + (qd0 + 1) * 32 + comp * 4) = hi23;
        *reinterpret_cast<uint32_t*>(ub + qd0 * 32 + 16 + comp * 4) = lo01;
        *reinterpret_cast<uint32_t*>(ub + (qd0 + 1) * 32 + 16 + comp * 4) = lo23;
    }

    float4 oacc[2][4];
    float lacc[2][2];
#pragma unroll
    for (int m = 0; m < 2; m++) {
        lacc[m][0] = 0.f; lacc[m][1] = 0.f;
#pragma unroll
        for (int j = 0; j < 4; j++) oacc[m][j] = make_float4(0.f, 0.f, 0.f, 0.f);
    }

    const int u0 = (rslot * 2) * 8 + grp;
    const int u1 = (rslot * 2 + 1) * 8 + grp;
    const int j0 = half ? (qb + 1) : 0;
    const int j1 = half ? (2 * qb + 1) : qb;

    // prologue: kick K(j0) then V(j0)
    {
        const char* gK = reinterpret_cast<const char*>(g_kimg + (h * 64 + j0) * KIMG_F4);
        for (int i = tid; i < KIMG_F4; i += 256) cp16(sb + KB_OFF + i * 16, gK + i * 16);
        CP_COMMIT();
        const char* gV = reinterpret_cast<const char*>(g_vimg + (h * 64 + j0) * VIMG_F4);
        for (int i = tid; i < VIMG_F4; i += 256) cp16(sb + VP_OFF + i * 16, gV + i * 16);
        CP_COMMIT();
    }
    __syncthreads();   // Q pack visible

    for (int jt = j0; jt <= j1; ++jt) {
        CP_WAIT1();        // K(jt) landed (V(jt) may pend)
        __syncthreads();   // all threads' K copies visible

        // ---- GEMM1: S = Q K^T (bf16: hi*hi + lo*hi + hi*lo) ----
        float4 sacc[2][4];
#pragma unroll
        for (int m = 0; m < 2; m++)
#pragma unroll
            for (int n = 0; n < 4; n++) sacc[m][n] = make_float4(0.f, 0.f, 0.f, 0.f);

#pragma unroll
        for (int kt = 0; kt < 4; kt++) {
            const char* qp0 = sm + QB_OFF + u0 * 528 + kt * 128 + qd * 32;
            const char* qp1 = sm + QB_OFF + u1 * 528 + kt * 128 + qd * 32;
            uint4 qh0 = *reinterpret_cast<const uint4*>(qp0);
            uint4 ql0 = *reinterpret_cast<const uint4*>(qp0 + 16);
            uint4 qh1 = *reinterpret_cast<const uint4*>(qp1);
            uint4 ql1 = *reinterpret_cast<const uint4*>(qp1 + 16);
#pragma unroll
            for (int n = 0; n < 4; n++) {
                uint4 kf = *reinterpret_cast<const uint4*>(
                    sm + KB_OFF + ((ch * 4 + n) * 8 + grp) * 320 + kt * 64 + qd * 16);
                mma_bf16(sacc[0][n], qh0.x, qh0.y, qh0.z, qh0.w, kf.x, kf.y);
                mma_bf16(sacc[0][n], ql0.x, ql0.y, ql0.z, ql0.w, kf.x, kf.y);
                mma_bf16(sacc[0][n], qh0.x, qh0.y, qh0.z, qh0.w, kf.z, kf.w);
                mma_bf16(sacc[1][n], qh1.x, qh1.y, qh1.z, qh1.w, kf.x, kf.y);
                mma_bf16(sacc[1][n], ql1.x, ql1.y, ql1.z, ql1.w, kf.x, kf.y);
                mma_bf16(sacc[1][n], qh1.x, qh1.y, qh1.z, qh1.w, kf.z, kf.w);
            }
        }
        __syncthreads();   // K fully consumed

        // prefetch K(jt+1) — lands during exp + GEMM2
        if (jt < j1) {
            const char* gK = reinterpret_cast<const char*>(g_kimg + (h * 64 + jt + 1) * KIMG_F4);
            for (int i = tid; i < KIMG_F4; i += 256) cp16(sb + KB_OFF + i * 16, gK + i * 16);
            CP_COMMIT();
        }

        // ---- exp2 (+causal mask), P store (tf32), row sums ----
        const bool domask = (jt >= 2 * qb);
#pragma unroll
        for (int m = 0; m < 2; m++) {
            float rsA = 0.f, rsB = 0.f;
            int rA = (rslot * 2 + m) * 16 + grp;
            int gA = qbase + rA, gB = gA + 8;
#pragma unroll
            for (int n = 0; n < 4; n++) {
                int col0 = jt * 64 + (ch * 4 + n) * 8 + 2 * qd;
                float e0, e1, e2, e3;
                if (domask) {
                    e0 = (col0     <= gA) ? exp2f(sacc[m][n].x) : 0.f;
                    e1 = (col0 + 1 <= gA) ? exp2f(sacc[m][n].y) : 0.f;
                    e2 = (col0     <= gB) ? exp2f(sacc[m][n].z) : 0.f;
                    e3 = (col0 + 1 <= gB) ? exp2f(sacc[m][n].w) : 0.f;
                } else {
                    e0 = exp2f(sacc[m][n].x); e1 = exp2f(sacc[m][n].y);
                    e2 = exp2f(sacc[m][n].z); e3 = exp2f(sacc[m][n].w);
                }
                rsA += e0 + e1; rsB += e2 + e3;
                *reinterpret_cast<float4*>(
                    sm + PP_OFF + ((rslot * 2 + m) * 8 + grp) * 544 + (ch * 4 + n) * 64 + qd * 16) =
                    make_float4(tf32_rna(e0), tf32_rna(e2), tf32_rna(e1), tf32_rna(e3));
            }
            rsA += __shfl_xor_sync(0xffffffffu, rsA, 1);
            rsA += __shfl_xor_sync(0xffffffffu, rsA, 2);
            rsB += __shfl_xor_sync(0xffffffffu, rsB, 1);
            rsB += __shfl_xor_sync(0xffffffffu, rsB, 2);
            if (qd == 0) {
                float* lp = reinterpret_cast<float*>(sm + LP_OFF);
                lp[ch * 128 + rA] = rsA;
                lp[ch * 128 + rA + 8] = rsB;
            }
        }
        CP_WAIT1();        // V(jt) landed (K(jt+1) may pend)
        __syncthreads();   // P, L, V visible to all

        // ---- GEMM2: O += P V (tf32) ----
#pragma unroll
        for (int kc = 0; kc < 8; kc++) {
            const char* p0 = sm + PP_OFF + u0 * 544 + kc * 64 + qd * 8;
            const char* p1 = sm + PP_OFF + u1 * 544 + kc * 64 + qd * 8;
            float2 a01 = *reinterpret_cast<const float2*>(p0);
            float2 a23 = *reinterpret_cast<const float2*>(p0 + 32);
            float2 b01 = *reinterpret_cast<const float2*>(p1);
            float2 b23 = *reinterpret_cast<const float2*>(p1 + 32);
#pragma unroll
            for (int j = 0; j < 4; j++) {
                float2 vv2 = *reinterpret_cast<const float2*>(
                    sm + VP_OFF + ((ch * 4 + j) * 8 + grp) * 288 + kc * 32 + qd * 8);
                mma_tf32(oacc[0][j], a01.x, a01.y, a23.x, a23.y, vv2.x, vv2.y);
                mma_tf32(oacc[1][j], b01.x, b01.y, b23.x, b23.y, vv2.x, vv2.y);
            }
        }
        {
            const float* lp = reinterpret_cast<const float*>(sm + LP_OFF);
#pragma unroll
            for (int m = 0; m < 2; m++) {
                int rA = (rslot * 2 + m) * 16 + grp;
                lacc[m][0] += lp[rA] + lp[128 + rA];
                lacc[m][1] += lp[rA + 8] + lp[128 + rA + 8];
            }
        }
        __syncthreads();   // V fully consumed

        // prefetch V(jt+1) — lands during next GEMM1
        if (jt < j1) {
            const char* gV = reinterpret_cast<const char*>(g_vimg + (h * 64 + jt + 1) * VIMG_F4);
            for (int i = tid; i < VIMG_F4; i += 256) cp16(sb + VP_OFF + i * 16, gV + i * 16);
            CP_COMMIT();
        }
    }

    // ---- write partials to scratch ----
    const int tile = h * 32 + qb;
    const int p = tile * 2 + half;
    float* Os = g_scrO + p * 8192;
#pragma unroll
    for (int m = 0; m < 2; m++) {
        int rA = (rslot * 2 + m) * 16 + grp, rB = rA + 8;
#pragma unroll
        for (int j = 0; j < 4; j++) {
            int db = (ch * 4 + j) * 8 + 2 * qd;
            *reinterpret_cast<float2*>(&Os[rA * 64 + db]) = make_float2(oacc[m][j].x, oacc[m][j].y);
            *reinterpret_cast<float2*>(&Os[rB * 64 + db]) = make_float2(oacc[m][j].z, oacc[m][j].w);
        }
        if (qd == 0) {
            g_scrL[p * 128 + rA] = lacc[m][0];
            g_scrL[p * 128 + rB] = lacc[m][1];
        }
    }

    // ---- fused combine: second CTA of the pair finishes the tile ----
    __threadfence();
    __syncthreads();
    if (tid == 0) s_old = atomicAdd(&g_flags[tile], 1);
    __syncthreads();
    if (s_old == 1) {
        __threadfence();   // acquire: pair's scratch writes now visible
        const int p0 = tile * 2, p1 = p0 + 1;
        if (tid < 128) {
            float l = g_scrL[p0 * 128 + tid] + g_scrL[p1 * 128 + tid];
            inv_s[tid] = 1.f / l;
            lse_s[tid] = logf(l);
        }
        __syncthreads();
        const float4* A = reinterpret_cast<const float4*>(g_scrO + p0 * 8192);
        const float4* B = reinterpret_cast<const float4*>(g_scrO + p1 * 8192);
#pragma unroll
        for (int i = 0; i < 8; i++) {
            int idx = tid + i * 256;
            int row = idx >> 4, d4 = (idx & 15) << 2;
            float4 a = A[idx], b = B[idx];
            float iv = inv_s[row];
            int sg = qbase + row;
            int c = sg >> 9;
            int rk = (c < 4) ? c : 7 - c;
            int sl = (c < 4) ? (sg & 511) : 512 + (sg & 511);
            *reinterpret_cast<float4*>(&out[rk * 524288 + sl * 512 + h * 64 + d4]) =
                make_float4((a.x + b.x) * iv, (a.y + b.y) * iv,
                            (a.z + b.z) * iv, (a.w + b.w) * iv);
        }
        if (tid < 128) {
            int sg = qbase + tid;
            int c = sg >> 9;
            int rk = (c < 4) ? c : 7 - c;
            int sl = (c < 4) ? (sg & 511) : 512 + (sg & 511);
            out[OUT_ELEMS + rk * 8192 + h * 1024 + sl] = lse_s[tid];
        }
        __syncthreads();
        if (tid == 0) g_flags[tile] = 0;   // reset for next graph replay
    }
}

extern "C" void kernel_launch(void* const* d_in, const int* in_sizes, int n_in,
                              void* d_out, int out_size)
{
    const float* q = (const float*)d_in[0];
    const float* k = (const float*)d_in[1];
    const float* v = (const float*)d_in[2];
    float* out = (float*)d_out;

    cudaFuncSetAttribute(zz_fa_part, cudaFuncAttributeMaxDynamicSharedMemorySize, SMEM_TOTAL);
    dim3 pgrid(64, NH);
    zz_prep<<<pgrid, 256, 40960>>>(k, v);
    zz_fa_part<<<512, 256, SMEM_TOTAL>>>(q, out);
}

// round 9
// speedup vs baseline: 1.5194x; 1.5194x over previous
#include <cuda_runtime.h>
#include <cuda_fp16.h>
#include <math.h>
#include <stdint.h>

#define NH 8
#define GROW 512            // gmem row stride (NH*HD)
#define OUT_ELEMS 2097152   // 4*1024*8*64
#define QB_OFF 0            // Q packed fp16 hi/lo: 64 units * 528B
#define KB_OFF 33792        // K fp16 fragments: 64 keys * 160B
#define VP_OFF 44032        // V fp16 fragments: 64 d * 160B
#define PP_OFF 54272        // P fp16: 128 rows * 160B
#define LP_OFF 74752        // row-sum partials: 2 * 128 floats
#define SMEM_TOTAL 75776
#define KIMG_F4 640         // 10240B / 16
#define VIMG_F4 640

__device__ float4 g_kimg[NH * 64 * KIMG_F4];   // packed K tile images
__device__ float4 g_vimg[NH * 64 * VIMG_F4];   // packed V tile images
__device__ float g_scrO[512 * 8192];           // partial O
__device__ float g_scrL[512 * 128];            // partial l

__device__ __forceinline__ void mma_fp16(float4& c,
    uint32_t a0, uint32_t a1, uint32_t a2, uint32_t a3, uint32_t b0, uint32_t b1)
{
    asm volatile(
        "mma.sync.aligned.m16n8k16.row.col.f32.f16.f16.f32 "
        "{%0,%1,%2,%3}, {%4,%5,%6,%7}, {%8,%9}, {%0,%1,%2,%3};\n"
        : "+f"(c.x), "+f"(c.y), "+f"(c.z), "+f"(c.w)
        : "r"(a0), "r"(a1), "r"(a2), "r"(a3), "r"(b0), "r"(b1));
}
__device__ __forceinline__ uint32_t pack2h(float a, float b) {
    __half2 t = __floats2half2_rn(a, b);
    return *reinterpret_cast<uint32_t*>(&t);
}
__device__ __forceinline__ uint32_t smem_u32(const void* p) {
    uint32_t a;
    asm("{ .reg .u64 t; cvta.to.shared.u64 t, %1; cvt.u32.u64 %0, t; }" : "=r"(a) : "l"(p));
    return a;
}
__device__ __forceinline__ void cp16(uint32_t saddr, const void* g) {
    asm volatile("cp.async.cg.shared.global [%0], [%1], 16;" :: "r"(saddr), "l"(g) : "memory");
}
#define CP_COMMIT() asm volatile("cp.async.commit_group;" ::: "memory")
#define CP_WAIT1()  asm volatile("cp.async.wait_group 1;" ::: "memory")

// fragment sub-offset of element w (0..15) inside a k16 chunk: {2qd,2qd+1,2qd+8,2qd+9}@qd*8
__device__ __forceinline__ int fragoff(int w) {
    return ((w & 7) >> 1) * 8 + ((w >> 3) & 1) * 4 + (w & 1) * 2;
}

// ---- prep: pack K/V tiles into gmem fragment images ----
__global__ __launch_bounds__(256) void zz_prep(
    const float* __restrict__ k, const float* __restrict__ v)
{
    extern __shared__ char sm[];
    const int tid = threadIdx.x;
    const int jt = blockIdx.x, h = blockIdx.y;
#pragma unroll
    for (int it = 0; it < 4; it++) {
        int idx = tid + it * 256;
        int key = idx >> 4, d4 = (idx & 15) << 2;
        int goff = (jt * 64 + key) * GROW + h * 64 + d4;
        float4 kv = *reinterpret_cast<const float4*>(&k[goff]);
        float4 vv = *reinterpret_cast<const float4*>(&v[goff]);
        float ka[4] = {kv.x, kv.y, kv.z, kv.w};
        float va[4] = {vv.x, vv.y, vv.z, vv.w};
#pragma unroll
        for (int j = 0; j < 4; j++) {
            int d = d4 + j;
            // K: row=key (n dim), contraction = d
            *reinterpret_cast<__half*>(sm + key * 160 + (d >> 4) * 32 + fragoff(d & 15)) =
                __float2half_rn(ka[j]);
            // V: row=d (n dim), contraction = key
            *reinterpret_cast<__half*>(sm + 10240 + d * 160 + (key >> 4) * 32 + fragoff(key & 15)) =
                __float2half_rn(va[j]);
        }
    }
    __syncthreads();
    float4* dstK = g_kimg + (h * 64 + jt) * KIMG_F4;
    const float4* srcK = reinterpret_cast<const float4*>(sm);
    for (int i = tid; i < KIMG_F4; i += 256) dstK[i] = srcK[i];
    float4* dstV = g_vimg + (h * 64 + jt) * VIMG_F4;
    const float4* srcV = reinterpret_cast<const float4*>(sm + 10240);
    for (int i = tid; i < VIMG_F4; i += 256) dstV[i] = srcV[i];
}

__global__ __launch_bounds__(256, 2) void zz_fa_part(
    const float* __restrict__ q)
{
    extern __shared__ char sm[];
    const uint32_t sb = smem_u32(sm);
    const int tid = threadIdx.x;
    const int w = tid >> 5, lane = tid & 31, grp = lane >> 2, qd = lane & 3;
    const int rslot = w >> 1, ch = w & 1;
    const int bx = blockIdx.x;
    const int qb = 31 - (bx >> 4);        // heavy q-tiles first
    const int h = (bx >> 1) & 7;
    const int half = bx & 1;
    const int qbase = qb * 128;

    // ---- pack Q once (scale * log2e folded in, fp16 hi/lo split) ----
    const float qscale = 0.125f * 1.4426950408889634f;
    for (int idx = tid; idx < 2048; idx += 256) {
        int row = idx >> 4, d4 = (idx & 15) << 2;
        float4 qv = *reinterpret_cast<const float4*>(&q[(qbase + row) * GROW + h * 64 + d4]);
        float f0 = qv.x * qscale, f1 = qv.y * qscale, f2 = qv.z * qscale, f3 = qv.w * qscale;
        __half2 h01 = __floats2half2_rn(f0, f1);
        __half2 h23 = __floats2half2_rn(f2, f3);
        uint32_t hi01 = *reinterpret_cast<uint32_t*>(&h01);
        uint32_t hi23 = *reinterpret_cast<uint32_t*>(&h23);
        uint32_t lo01 = pack2h(f0 - __half2float(h01.x), f1 - __half2float(h01.y));
        uint32_t lo23 = pack2h(f2 - __half2float(h23.x), f3 - __half2float(h23.y));
        int mt = row >> 4, g = row & 7, rh = (row >> 3) & 1;
        int kt = d4 >> 4, dp = d4 & 15, hf = dp >> 3, qd0 = (dp & 7) >> 1;
        int comp = hf * 2 + rh;
        char* ub = sm + QB_OFF + (mt * 8 + g) * 528 + kt * 128;
        *reinterpret_cast<uint32_t*>(ub + qd0 * 32 + comp * 4) = hi01;
        *reinterpret_cast<uint32_t*>(ub + (qd0 + 1) * 32 + comp * 4) = hi23;
        *reinterpret_cast<uint32_t*>(ub + qd0 * 32 + 16 + comp * 4) = lo01;
        *reinterpret_cast<uint32_t*>(ub + (qd0 + 1) * 32 + 16 + comp * 4) = lo23;
    }

    float4 oacc[2][4];
    float lacc[2][2];
#pragma unroll
    for (int m = 0; m < 2; m++) {
        lacc[m][0] = 0.f; lacc[m][1] = 0.f;
#pragma unroll
        for (int j = 0; j < 4; j++) oacc[m][j] = make_float4(0.f, 0.f, 0.f, 0.f);
    }

    const int u0 = (rslot * 2) * 8 + grp;     // Q pack unit for m-tile 0
    const int u1 = (rslot * 2 + 1) * 8 + grp; // m-tile 1
    const int j0 = half ? (qb + 1) : 0;
    const int j1 = half ? (2 * qb + 1) : qb;

    // prologue: kick K(j0) then V(j0)
    {
        const char* gK = reinterpret_cast<const char*>(g_kimg + (h * 64 + j0) * KIMG_F4);
        for (int i = tid; i < KIMG_F4; i += 256) cp16(sb + KB_OFF + i * 16, gK + i * 16);
        CP_COMMIT();
        const char* gV = reinterpret_cast<const char*>(g_vimg + (h * 64 + j0) * VIMG_F4);
        for (int i = tid; i < VIMG_F4; i += 256) cp16(sb + VP_OFF + i * 16, gV + i * 16);
        CP_COMMIT();
    }
    __syncthreads();   // Q pack visible

    for (int jt = j0; jt <= j1; ++jt) {
        CP_WAIT1();        // K(jt) landed (V(jt) may pend)
        __syncthreads();

        // ---- GEMM1: S = Q K^T (fp16 2-pass: hi*k + lo*k) ----
        float4 sacc[2][4];
#pragma unroll
        for (int m = 0; m < 2; m++)
#pragma unroll
            for (int n = 0; n < 4; n++) sacc[m][n] = make_float4(0.f, 0.f, 0.f, 0.f);

#pragma unroll
        for (int kt = 0; kt < 4; kt++) {
            const char* qp0 = sm + QB_OFF + u0 * 528 + kt * 128 + qd * 32;
            const char* qp1 = sm + QB_OFF + u1 * 528 + kt * 128 + qd * 32;
            uint4 qh0 = *reinterpret_cast<const uint4*>(qp0);
            uint4 ql0 = *reinterpret_cast<const uint4*>(qp0 + 16);
            uint4 qh1 = *reinterpret_cast<const uint4*>(qp1);
            uint4 ql1 = *reinterpret_cast<const uint4*>(qp1 + 16);
#pragma unroll
            for (int n = 0; n < 4; n++) {
                uint2 kf = *reinterpret_cast<const uint2*>(
                    sm + KB_OFF + ((ch * 4 + n) * 8 + grp) * 160 + kt * 32 + qd * 8);
                mma_fp16(sacc[0][n], qh0.x, qh0.y, qh0.z, qh0.w, kf.x, kf.y);
                mma_fp16(sacc[0][n], ql0.x, ql0.y, ql0.z, ql0.w, kf.x, kf.y);
                mma_fp16(sacc[1][n], qh1.x, qh1.y, qh1.z, qh1.w, kf.x, kf.y);
                mma_fp16(sacc[1][n], ql1.x, ql1.y, ql1.z, ql1.w, kf.x, kf.y);
            }
        }
        __syncthreads();   // K fully consumed

        // prefetch K(jt+1)
        if (jt < j1) {
            const char* gK = reinterpret_cast<const char*>(g_kimg + (h * 64 + jt + 1) * KIMG_F4);
            for (int i = tid; i < KIMG_F4; i += 256) cp16(sb + KB_OFF + i * 16, gK + i * 16);
            CP_COMMIT();
        }

        // ---- exp2 (+causal mask), P store (fp16 fragments), row sums ----
        const bool domask = (jt >= 2 * qb);
#pragma unroll
        for (int m = 0; m < 2; m++) {
            float rsA = 0.f, rsB = 0.f;
            int rA = 32 * rslot + 16 * m + grp;   // row of .x/.y
            int gA = qbase + rA, gB = gA + 8;
#pragma unroll
            for (int n = 0; n < 4; n++) {
                int col0 = jt * 64 + (ch * 4 + n) * 8 + 2 * qd;
                float e0, e1, e2, e3;
                if (domask) {
                    e0 = (col0     <= gA) ? exp2f(sacc[m][n].x) : 0.f;
                    e1 = (col0 + 1 <= gA) ? exp2f(sacc[m][n].y) : 0.f;
                    e2 = (col0     <= gB) ? exp2f(sacc[m][n].z) : 0.f;
                    e3 = (col0 + 1 <= gB) ? exp2f(sacc[m][n].w) : 0.f;
                } else {
                    e0 = exp2f(sacc[m][n].x); e1 = exp2f(sacc[m][n].y);
                    e2 = exp2f(sacc[m][n].z); e3 = exp2f(sacc[m][n].w);
                }
                rsA += e0 + e1; rsB += e2 + e3;
                int kc = 2 * ch + (n >> 1), nb = n & 1;
                char* pA = sm + PP_OFF + rA * 160 + kc * 32 + qd * 8 + nb * 4;
                *reinterpret_cast<__half2*>(pA) = __floats2half2_rn(e0, e1);
                *reinterpret_cast<__half2*>(pA + 8 * 160) = __floats2half2_rn(e2, e3);
            }
            rsA += __shfl_xor_sync(0xffffffffu, rsA, 1);
            rsA += __shfl_xor_sync(0xffffffffu, rsA, 2);
            rsB += __shfl_xor_sync(0xffffffffu, rsB, 1);
            rsB += __shfl_xor_sync(0xffffffffu, rsB, 2);
            if (qd == 0) {
                float* lp = reinterpret_cast<float*>(sm + LP_OFF);
                lp[ch * 128 + rA] = rsA;
                lp[ch * 128 + rA + 8] = rsB;
            }
        }
        CP_WAIT1();        // V(jt) landed
        __syncthreads();   // P, L, V visible

        // ---- GEMM2: O += P V (fp16 m16n8k16) ----
#pragma unroll
        for (int kc = 0; kc < 4; kc++) {
            const char* pa = sm + PP_OFF + (32 * rslot + grp) * 160 + kc * 32 + qd * 8;
            uint2 A0 = *reinterpret_cast<const uint2*>(pa);            // m0: row rA {k01,k89}
            uint2 A1 = *reinterpret_cast<const uint2*>(pa + 8 * 160);  // m0: row rB
            uint2 B0 = *reinterpret_cast<const uint2*>(pa + 16 * 160); // m1: row rA
            uint2 B1 = *reinterpret_cast<const uint2*>(pa + 24 * 160); // m1: row rB
#pragma unroll
            for (int j = 0; j < 4; j++) {
                uint2 vf = *reinterpret_cast<const uint2*>(
                    sm + VP_OFF + ((ch * 4 + j) * 8 + grp) * 160 + kc * 32 + qd * 8);
                mma_fp16(oacc[0][j], A0.x, A1.x, A0.y, A1.y, vf.x, vf.y);
                mma_fp16(oacc[1][j], B0.x, B1.x, B0.y, B1.y, vf.x, vf.y);
            }
        }
        {
            const float* lp = reinterpret_cast<const float*>(sm + LP_OFF);
#pragma unroll
            for (int m = 0; m < 2; m++) {
                int rA = 32 * rslot + 16 * m + grp;
                lacc[m][0] += lp[rA] + lp[128 + rA];
                lacc[m][1] += lp[rA + 8] + lp[128 + rA + 8];
            }
        }
        __syncthreads();   // V/P fully consumed

        // prefetch V(jt+1)
        if (jt < j1) {
            const char* gV = reinterpret_cast<const char*>(g_vimg + (h * 64 + jt + 1) * VIMG_F4);
            for (int i = tid; i < VIMG_F4; i += 256) cp16(sb + VP_OFF + i * 16, gV + i * 16);
            CP_COMMIT();
        }
    }

    // ---- write partials to scratch ----
    const int p = (h * 32 + qb) * 2 + half;
    float* Os = g_scrO + p * 8192;
#pragma unroll
    for (int m = 0; m < 2; m++) {
        int rA = 32 * rslot + 16 * m + grp, rB = rA + 8;
#pragma unroll
        for (int j = 0; j < 4; j++) {
            int db = (ch * 4 + j) * 8 + 2 * qd;
            *reinterpret_cast<float2*>(&Os[rA * 64 + db]) = make_float2(oacc[m][j].x, oacc[m][j].y);
            *reinterpret_cast<float2*>(&Os[rB * 64 + db]) = make_float2(oacc[m][j].z, oacc[m][j].w);
        }
        if (qd == 0) {
            g_scrL[p * 128 + rA] = lacc[m][0];
            g_scrL[p * 128 + rB] = lacc[m][1];
        }
    }
}

__global__ __launch_bounds__(256) void zz_fa_combine(float* __restrict__ out)
{
    __shared__ float inv_s[128];
    __shared__ float lse_s[128];
    const int b = blockIdx.x;
    const int qt = b >> 3, h = b & 7;
    const int p0 = (h * 32 + qt) * 2, p1 = p0 + 1;
    const int t = threadIdx.x;
    if (t < 128) {
        float l = g_scrL[p0 * 128 + t] + g_scrL[p1 * 128 + t];
        inv_s[t] = 1.f / l;
        lse_s[t] = logf(l);
    }
    __syncthreads();
    const float4* A = reinterpret_cast<const float4*>(g_scrO + p0 * 8192);
    const float4* B = reinterpret_cast<const float4*>(g_scrO + p1 * 8192);
#pragma unroll
    for (int i = 0; i < 8; i++) {
        int idx = t + i * 256;
        int row = idx >> 4, d4 = (idx & 15) << 2;
        float4 a = A[idx], bb = B[idx];
        float iv = inv_s[row];
        int sg = qt * 128 + row;
        int c = sg >> 9;
        int rk = (c < 4) ? c : 7 - c;
        int sl = (c < 4) ? (sg & 511) : 512 + (sg & 511);
        *reinterpret_cast<float4*>(&out[rk * 524288 + sl * 512 + h * 64 + d4]) =
            make_float4((a.x + bb.x) * iv, (a.y + bb.y) * iv,
                        (a.z + bb.z) * iv, (a.w + bb.w) * iv);
    }
    if (t < 128) {
        int sg = qt * 128 + t;
        int c = sg >> 9;
        int rk = (c < 4) ? c : 7 - c;
        int sl = (c < 4) ? (sg & 511) : 512 + (sg & 511);
        out[OUT_ELEMS + rk * 8192 + h * 1024 + sl] = lse_s[t];
    }
}

extern "C" void kernel_launch(void* const* d_in, const int* in_sizes, int n_in,
                              void* d_out, int out_size)
{
    const float* q = (const float*)d_in[0];
    const float* k = (const float*)d_in[1];
    const float* v = (const float*)d_in[2];
    float* out = (float*)d_out;

    cudaFuncSetAttribute(zz_fa_part, cudaFuncAttributeMaxDynamicSharedMemorySize, SMEM_TOTAL);
    dim3 pgrid(64, NH);
    zz_prep<<<pgrid, 256, 20480>>>(k, v);
    zz_fa_part<<<512, 256, SMEM_TOTAL>>>(q);
    zz_fa_combine<<<256, 256>>>(out);
}

// round 11
// speedup vs baseline: 1.5459x; 1.0174x over previous
#include <cuda_runtime.h>
#include <cuda_fp16.h>
#include <math.h>
#include <stdint.h>

#define NH 8
#define GROW 512            // gmem row stride (NH*HD)
#define OUT_ELEMS 2097152   // 4*1024*8*64
#define QB_OFF 0            // Q packed fp16 hi/lo: 64 units * 528B
#define K_OFF(b) (33792 + (b) * 10240)   // K fp16 fragments, double-buffered
#define V_OFF(b) (54272 + (b) * 10240)   // V fp16 fragments, double-buffered
#define PP_OFF 74752        // P fp16: 128 rows * 160B
#define LP_OFF 95232        // row-sum partials: 2 * 128 floats
#define SMEM_TOTAL 96256
#define KIMG_F4 640         // 10240B / 16
#define VIMG_F4 640

__device__ float4 g_kimg[NH * 64 * KIMG_F4];   // packed K tile images
__device__ float4 g_vimg[NH * 64 * VIMG_F4];   // packed V tile images
__device__ float g_scrO[512 * 8192];           // partial O
__device__ float g_scrL[512 * 128];            // partial l

__device__ __forceinline__ void mma_fp16(float4& c,
    uint32_t a0, uint32_t a1, uint32_t a2, uint32_t a3, uint32_t b0, uint32_t b1)
{
    asm volatile(
        "mma.sync.aligned.m16n8k16.row.col.f32.f16.f16.f32 "
        "{%0,%1,%2,%3}, {%4,%5,%6,%7}, {%8,%9}, {%0,%1,%2,%3};\n"
        : "+f"(c.x), "+f"(c.y), "+f"(c.z), "+f"(c.w)
        : "r"(a0), "r"(a1), "r"(a2), "r"(a3), "r"(b0), "r"(b1));
}
__device__ __forceinline__ uint32_t pack2h(float a, float b) {
    __half2 t = __floats2half2_rn(a, b);
    return *reinterpret_cast<uint32_t*>(&t);
}
__device__ __forceinline__ uint32_t smem_u32(const void* p) {
    uint32_t a;
    asm("{ .reg .u64 t; cvta.to.shared.u64 t, %1; cvt.u32.u64 %0, t; }" : "=r"(a) : "l"(p));
    return a;
}
__device__ __forceinline__ void cp16(uint32_t saddr, const void* g) {
    asm volatile("cp.async.cg.shared.global [%0], [%1], 16;" :: "r"(saddr), "l"(g) : "memory");
}
#define CP_COMMIT() asm volatile("cp.async.commit_group;" ::: "memory")
#define CP_WAIT1()  asm volatile("cp.async.wait_group 1;" ::: "memory")

// fragment sub-offset of element w (0..15) inside a k16 chunk
__device__ __forceinline__ int fragoff(int w) {
    return ((w & 7) >> 1) * 8 + ((w >> 3) & 1) * 4 + (w & 1) * 2;
}

// ---- prep: pack K/V tiles into gmem fragment images (key-half per CTA) ----
__global__ __launch_bounds__(256) void zz_prep(
    const float* __restrict__ k, const float* __restrict__ v)
{
    extern __shared__ char sm[];     // [0,5120): K half-image; [5120,9216): V compact
    const int tid = threadIdx.x;
    const int jt = blockIdx.x, h = blockIdx.y, kh = blockIdx.z;
    const int kb = kh * 32;

    float4 kr[2], vr[2];
    int keyl[2], dd4[2];
#pragma unroll
    for (int it = 0; it < 2; it++) {
        int idx = tid + it * 256;
        keyl[it] = idx >> 4;
        dd4[it] = (idx & 15) << 2;
        int goff = (jt * 64 + kb + keyl[it]) * GROW + h * 64 + dd4[it];
        kr[it] = *reinterpret_cast<const float4*>(&k[goff]);
        vr[it] = *reinterpret_cast<const float4*>(&v[goff]);
    }
#pragma unroll
    for (int it = 0; it < 2; it++) {
        float ka[4] = {kr[it].x, kr[it].y, kr[it].z, kr[it].w};
        float va[4] = {vr[it].x, vr[it].y, vr[it].z, vr[it].w};
#pragma unroll
        for (int j = 0; j < 4; j++) {
            int d = dd4[it] + j;
            *reinterpret_cast<__half*>(sm + keyl[it] * 160 + (d >> 4) * 32 + fragoff(d & 15)) =
                __float2half_rn(ka[j]);
            *reinterpret_cast<__half*>(sm + 5120 + d * 64 + (keyl[it] >> 4) * 32 + fragoff(keyl[it] & 15)) =
                __float2half_rn(va[j]);
        }
    }
    __syncthreads();
    // K: contiguous 5120B at key-half offset
    float4* dstK = g_kimg + (h * 64 + jt) * KIMG_F4 + kh * 320;
    const float4* srcK = reinterpret_cast<const float4*>(sm);
#pragma unroll
    for (int i = tid; i < 320; i += 256) dstK[i] = srcK[i];
    // V: 64B per d-row at offset kh*64 inside each 160B row
    float4* dstV = g_vimg + (h * 64 + jt) * VIMG_F4;
    const float4* srcV = reinterpret_cast<const float4*>(sm + 5120);
    {
        int d = tid >> 2, c = tid & 3;
        dstV[d * 10 + kh * 4 + c] = srcV[d * 4 + c];
    }
}

__global__ __launch_bounds__(256, 2) void zz_fa_part(
    const float* __restrict__ q)
{
    extern __shared__ char sm[];
    const uint32_t sb = smem_u32(sm);
    const int tid = threadIdx.x;
    const int w = tid >> 5, lane = tid & 31, grp = lane >> 2, qd = lane & 3;
    const int rslot = w >> 1, ch = w & 1;
    const int bx = blockIdx.x;
    const int qb = 31 - (bx >> 4);        // heavy q-tiles first
    const int h = (bx >> 1) & 7;
    const int half = bx & 1;
    const int qbase = qb * 128;

    // ---- pack Q once (scale * log2e folded in, fp16 hi/lo split) ----
    const float qscale = 0.125f * 1.4426950408889634f;
    for (int idx = tid; idx < 2048; idx += 256) {
        int row = idx >> 4, d4 = (idx & 15) << 2;
        float4 qv = *reinterpret_cast<const float4*>(&q[(qbase + row) * GROW + h * 64 + d4]);
        float f0 = qv.x * qscale, f1 = qv.y * qscale, f2 = qv.z * qscale, f3 = qv.w * qscale;
        __half2 h01 = __floats2half2_rn(f0, f1);
        __half2 h23 = __floats2half2_rn(f2, f3);
        uint32_t hi01 = *reinterpret_cast<uint32_t*>(&h01);
        uint32_t hi23 = *reinterpret_cast<uint32_t*>(&h23);
        uint32_t lo01 = pack2h(f0 - __half2float(h01.x), f1 - __half2float(h01.y));
        uint32_t lo23 = pack2h(f2 - __half2float(h23.x), f3 - __half2float(h23.y));
        int mt = row >> 4, g = row & 7, rh = (row >> 3) & 1;
        int kt = d4 >> 4, dp = d4 & 15, hf = dp >> 3, qd0 = (dp & 7) >> 1;
        int comp = hf * 2 + rh;
        char* ub = sm + QB_OFF + (mt * 8 + g) * 528 + kt * 128;
        *reinterpret_cast<uint32_t*>(ub + qd0 * 32 + comp * 4) = hi01;
        *reinterpret_cast<uint32_t*>(ub + (qd0 + 1) * 32 + comp * 4) = hi23;
        *reinterpret_cast<uint32_t*>(ub + qd0 * 32 + 16 + comp * 4) = lo01;
        *reinterpret_cast<uint32_t*>(ub + (qd0 + 1) * 32 + 16 + comp * 4) = lo23;
    }

    float4 oacc[2][4];
    float lacc[2][2];
#pragma unroll
    for (int m = 0; m < 2; m++) {
        lacc[m][0] = 0.f; lacc[m][1] = 0.f;
#pragma unroll
        for (int j = 0; j < 4; j++) oacc[m][j] = make_float4(0.f, 0.f, 0.f, 0.f);
    }

    const int u0 = (rslot * 2) * 8 + grp;
    const int u1 = (rslot * 2 + 1) * 8 + grp;
    const int j0 = half ? (qb + 1) : 0;
    const int j1 = half ? (2 * qb + 1) : qb;

    // prologue: pair(j0) -> buf0, pair(j0+1) -> buf1 (or empty commit)
    {
        const char* gK = reinterpret_cast<const char*>(g_kimg + (h * 64 + j0) * KIMG_F4);
        const char* gV = reinterpret_cast<const char*>(g_vimg + (h * 64 + j0) * VIMG_F4);
        for (int i = tid; i < KIMG_F4; i += 256) cp16(sb + K_OFF(0) + i * 16, gK + i * 16);
        for (int i = tid; i < VIMG_F4; i += 256) cp16(sb + V_OFF(0) + i * 16, gV + i * 16);
        CP_COMMIT();
        if (j0 < j1) {
            const char* gK1 = reinterpret_cast<const char*>(g_kimg + (h * 64 + j0 + 1) * KIMG_F4);
            const char* gV1 = reinterpret_cast<const char*>(g_vimg + (h * 64 + j0 + 1) * VIMG_F4);
            for (int i = tid; i < KIMG_F4; i += 256) cp16(sb + K_OFF(1) + i * 16, gK1 + i * 16);
            for (int i = tid; i < VIMG_F4; i += 256) cp16(sb + V_OFF(1) + i * 16, gV1 + i * 16);
        }
        CP_COMMIT();
    }
    __syncthreads();   // Q pack visible

    for (int jt = j0; jt <= j1; ++jt) {
        const int b = (jt - j0) & 1;
        CP_WAIT1();        // pair(jt) landed (groups retire in commit order)
        __syncthreads();

        // ---- GEMM1: S = Q K^T (fp16 2-pass: hi*k + lo*k) ----
        float4 sacc[2][4];
#pragma unroll
        for (int m = 0; m < 2; m++)
#pragma unroll
            for (int n = 0; n < 4; n++) sacc[m][n] = make_float4(0.f, 0.f, 0.f, 0.f);

#pragma unroll
        for (int kt = 0; kt < 4; kt++) {
            const char* qp0 = sm + QB_OFF + u0 * 528 + kt * 128 + qd * 32;
            const char* qp1 = sm + QB_OFF + u1 * 528 + kt * 128 + qd * 32;
            uint4 qh0 = *reinterpret_cast<const uint4*>(qp0);
            uint4 ql0 = *reinterpret_cast<const uint4*>(qp0 + 16);
            uint4 qh1 = *reinterpret_cast<const uint4*>(qp1);
            uint4 ql1 = *reinterpret_cast<const uint4*>(qp1 + 16);
#pragma unroll
            for (int n = 0; n < 4; n++) {
                uint2 kf = *reinterpret_cast<const uint2*>(
                    sm + K_OFF(b) + ((ch * 4 + n) * 8 + grp) * 160 + kt * 32 + qd * 8);
                mma_fp16(sacc[0][n], qh0.x, qh0.y, qh0.z, qh0.w, kf.x, kf.y);
                mma_fp16(sacc[0][n], ql0.x, ql0.y, ql0.z, ql0.w, kf.x, kf.y);
                mma_fp16(sacc[1][n], qh1.x, qh1.y, qh1.z, qh1.w, kf.x, kf.y);
                mma_fp16(sacc[1][n], ql1.x, ql1.y, ql1.z, ql1.w, kf.x, kf.y);
            }
        }

        // ---- exp2 (+causal mask), P store (fp16 fragments), row sums ----
        const bool domask = (jt >= 2 * qb);
#pragma unroll
        for (int m = 0; m < 2; m++) {
            float rsA = 0.f, rsB = 0.f;
            int rA = 32 * rslot + 16 * m + grp;
            int gA = qbase + rA, gB = gA + 8;
#pragma unroll
            for (int n = 0; n < 4; n++) {
                int col0 = jt * 64 + (ch * 4 + n) * 8 + 2 * qd;
                float e0, e1, e2, e3;
                if (domask) {
                    e0 = (col0     <= gA) ? exp2f(sacc[m][n].x) : 0.f;
                    e1 = (col0 + 1 <= gA) ? exp2f(sacc[m][n].y) : 0.f;
                    e2 = (col0     <= gB) ? exp2f(sacc[m][n].z) : 0.f;
                    e3 = (col0 + 1 <= gB) ? exp2f(sacc[m][n].w) : 0.f;
                } else {
                    e0 = exp2f(sacc[m][n].x); e1 = exp2f(sacc[m][n].y);
                    e2 = exp2f(sacc[m][n].z); e3 = exp2f(sacc[m][n].w);
                }
                rsA += e0 + e1; rsB += e2 + e3;
                int kc = 2 * ch + (n >> 1), nb = n & 1;
                char* pA = sm + PP_OFF + rA * 160 + kc * 32 + qd * 8 + nb * 4;
                *reinterpret_cast<__half2*>(pA) = __floats2half2_rn(e0, e1);
                *reinterpret_cast<__half2*>(pA + 8 * 160) = __floats2half2_rn(e2, e3);
            }
            rsA += __shfl_xor_sync(0xffffffffu, rsA, 1);
            rsA += __shfl_xor_sync(0xffffffffu, rsA, 2);
            rsB += __shfl_xor_sync(0xffffffffu, rsB, 1);
            rsB += __shfl_xor_sync(0xffffffffu, rsB, 2);
            if (qd == 0) {
                float* lp = reinterpret_cast<float*>(sm + LP_OFF);
                lp[ch * 128 + rA] = rsA;
                lp[ch * 128 + rA + 8] = rsB;
            }
        }
        __syncthreads();   // P, L visible (V(jt) landed with the pair group)

        // ---- GEMM2: O += P V (fp16 m16n8k16) ----
#pragma unroll
        for (int kc = 0; kc < 4; kc++) {
            const char* pa = sm + PP_OFF + (32 * rslot + grp) * 160 + kc * 32 + qd * 8;
            uint2 A0 = *reinterpret_cast<const uint2*>(pa);
            uint2 A1 = *reinterpret_cast<const uint2*>(pa + 8 * 160);
            uint2 B0 = *reinterpret_cast<const uint2*>(pa + 16 * 160);
            uint2 B1 = *reinterpret_cast<const uint2*>(pa + 24 * 160);
#pragma unroll
            for (int j = 0; j < 4; j++) {
                uint2 vf = *reinterpret_cast<const uint2*>(
                    sm + V_OFF(b) + ((ch * 4 + j) * 8 + grp) * 160 + kc * 32 + qd * 8);
                mma_fp16(oacc[0][j], A0.x, A1.x, A0.y, A1.y, vf.x, vf.y);
                mma_fp16(oacc[1][j], B0.x, B1.x, B0.y, B1.y, vf.x, vf.y);
            }
        }
        {
            const float* lp = reinterpret_cast<const float*>(sm + LP_OFF);
#pragma unroll
            for (int m = 0; m < 2; m++) {
                int rA = 32 * rslot + 16 * m + grp;
                lacc[m][0] += lp[rA] + lp[128 + rA];
                lacc[m][1] += lp[rA + 8] + lp[128 + rA + 8];
            }
        }
        __syncthreads();   // buf b fully consumed

        // prefetch pair(jt+2) into buf b (or empty commit to keep invariant)
        if (jt + 2 <= j1) {
            const char* gK = reinterpret_cast<const char*>(g_kimg + (h * 64 + jt + 2) * KIMG_F4);
            const char* gV = reinterpret_cast<const char*>(g_vimg + (h * 64 + jt + 2) * VIMG_F4);
            for (int i = tid; i < KIMG_F4; i += 256) cp16(sb + K_OFF(b) + i * 16, gK + i * 16);
            for (int i = tid; i < VIMG_F4; i += 256) cp16(sb + V_OFF(b) + i * 16, gV + i * 16);
        }
        CP_COMMIT();
    }

    // ---- write partials to scratch ----
    const int p = (h * 32 + qb) * 2 + half;
    float* Os = g_scrO + p * 8192;
#pragma unroll
    for (int m = 0; m < 2; m++) {
        int rA = 32 * rslot + 16 * m + grp, rB = rA + 8;
#pragma unroll
        for (int j = 0; j < 4; j++) {
            int db = (ch * 4 + j) * 8 + 2 * qd;
            *reinterpret_cast<float2*>(&Os[rA * 64 + db]) = make_float2(oacc[m][j].x, oacc[m][j].y);
            *reinterpret_cast<float2*>(&Os[rB * 64 + db]) = make_float2(oacc[m][j].z, oacc[m][j].w);
        }
        if (qd == 0) {
            g_scrL[p * 128 + rA] = lacc[m][0];
            g_scrL[p * 128 + rB] = lacc[m][1];
        }
    }
}

__global__ __launch_bounds__(256) void zz_fa_combine(float* __restrict__ out)
{
    __shared__ float inv_s[64];
    __shared__ float lse_s[64];
    const int b = blockIdx.x;
    const int tile = b >> 1, rh = b & 1;
    const int qt = tile >> 3, h = tile & 7;
    const int p0 = (h * 32 + qt) * 2, p1 = p0 + 1;   // FIX: matches main's (h*32+qb)*2+half
    const int row0 = rh * 64;
    const int t = threadIdx.x;
    if (t < 64) {
        float l = g_scrL[p0 * 128 + row0 + t] + g_scrL[p1 * 128 + row0 + t];
        inv_s[t] = 1.f / l;
        lse_s[t] = logf(l);
    }
    __syncthreads();
    const float4* A = reinterpret_cast<const float4*>(g_scrO + p0 * 8192 + row0 * 64);
    const float4* B = reinterpret_cast<const float4*>(g_scrO + p1 * 8192 + row0 * 64);
    float4 av[4], bv[4];
#pragma unroll
    for (int i = 0; i < 4; i++) { av[i] = A[t + i * 256]; bv[i] = B[t + i * 256]; }
#pragma unroll
    for (int i = 0; i < 4; i++) {
        int idx = t + i * 256;
        int row = idx >> 4, d4 = (idx & 15) << 2;
        float iv = inv_s[row];
        int sg = qt * 128 + row0 + row;
        int c = sg >> 9;
        int rk = (c < 4) ? c : 7 - c;
        int sl = (c < 4) ? (sg & 511) : 512 + (sg & 511);
        *reinterpret_cast<float4*>(&out[rk * 524288 + sl * 512 + h * 64 + d4]) =
            make_float4((av[i].x + bv[i].x) * iv, (av[i].y + bv[i].y) * iv,
                        (av[i].z + bv[i].z) * iv, (av[i].w + bv[i].w) * iv);
    }
    if (t < 64) {
        int sg = qt * 128 + row0 + t;
        int c = sg >> 9;
        int rk = (c < 4) ? c : 7 - c;
        int sl = (c < 4) ? (sg & 511) : 512 + (sg & 511);
        out[OUT_ELEMS + rk * 8192 + h * 1024 + sl] = lse_s[t];
    }
}

extern "C" void kernel_launch(void* const* d_in, const int* in_sizes, int n_in,
                              void* d_out, int out_size)
{
    const float* q = (const float*)d_in[0];
    const float* k = (const float*)d_in[1];
    const float* v = (const float*)d_in[2];
    float* out = (float*)d_out;

    cudaFuncSetAttribute(zz_fa_part, cudaFuncAttributeMaxDynamicSharedMemorySize, SMEM_TOTAL);
    dim3 pgrid(64, NH, 2);
    zz_prep<<<pgrid, 256, 9216>>>(k, v);
    zz_fa_part<<<512, 256, SMEM_TOTAL>>>(q);
    zz_fa_combine<<<512, 256>>>(out);
}

// round 12
// speedup vs baseline: 1.8081x; 1.1696x over previous
#include <cuda_runtime.h>
#include <cuda_fp16.h>
#include <math.h>
#include <stdint.h>

#define NH 8
#define GROW 512            // gmem row stride (NH*HD)
#define OUT_ELEMS 2097152   // 4*1024*8*64
#define QB_OFF 0            // Q packed fp16: 64 units * 528B (hi slots only)
#define K_OFF(b) (33792 + (b) * 10240)   // K fp16 fragments, double-buffered
#define V_OFF(b) (54272 + (b) * 10240)   // V fp16 fragments, double-buffered
#define PP_OFF 74752        // P fp16: 128 rows * 160B
#define LP_OFF 95232        // row-sum partials: 2 * 128 floats
#define SMEM_TOTAL 96256
#define KIMG_F4 640         // 10240B / 16
#define VIMG_F4 640

__device__ float4 g_kimg[NH * 64 * KIMG_F4];   // packed K tile images
__device__ float4 g_vimg[NH * 64 * VIMG_F4];   // packed V tile images
__device__ float g_scrO[512 * 8192];           // partial O
__device__ float g_scrL[512 * 128];            // partial l

__device__ __forceinline__ void mma_fp16(float4& c,
    uint32_t a0, uint32_t a1, uint32_t a2, uint32_t a3, uint32_t b0, uint32_t b1)
{
    asm volatile(
        "mma.sync.aligned.m16n8k16.row.col.f32.f16.f16.f32 "
        "{%0,%1,%2,%3}, {%4,%5,%6,%7}, {%8,%9}, {%0,%1,%2,%3};\n"
        : "+f"(c.x), "+f"(c.y), "+f"(c.z), "+f"(c.w)
        : "r"(a0), "r"(a1), "r"(a2), "r"(a3), "r"(b0), "r"(b1));
}
__device__ __forceinline__ uint32_t smem_u32(const void* p) {
    uint32_t a;
    asm("{ .reg .u64 t; cvta.to.shared.u64 t, %1; cvt.u32.u64 %0, t; }" : "=r"(a) : "l"(p));
    return a;
}
__device__ __forceinline__ void cp16(uint32_t saddr, const void* g) {
    asm volatile("cp.async.cg.shared.global [%0], [%1], 16;" :: "r"(saddr), "l"(g) : "memory");
}
#define CP_COMMIT() asm volatile("cp.async.commit_group;" ::: "memory")
#define CP_WAIT1()  asm volatile("cp.async.wait_group 1;" ::: "memory")
#define PAIR_BAR(id) asm volatile("bar.sync %0, 64;" :: "r"(id) : "memory")

// fragment sub-offset of element w (0..15) inside a k16 chunk
__device__ __forceinline__ int fragoff(int w) {
    return ((w & 7) >> 1) * 8 + ((w >> 3) & 1) * 4 + (w & 1) * 2;
}

// ---- prep: pack K/V tiles into gmem fragment images (key-half per CTA) ----
__global__ __launch_bounds__(256) void zz_prep(
    const float* __restrict__ k, const float* __restrict__ v)
{
    extern __shared__ char sm[];     // [0,5120): K half-image; [5120,9216): V compact
    const int tid = threadIdx.x;
    const int jt = blockIdx.x, h = blockIdx.y, kh = blockIdx.z;
    const int kb = kh * 32;

    float4 kr[2], vr[2];
    int keyl[2], dd4[2];
#pragma unroll
    for (int it = 0; it < 2; it++) {
        int idx = tid + it * 256;
        keyl[it] = idx >> 4;
        dd4[it] = (idx & 15) << 2;
        int goff = (jt * 64 + kb + keyl[it]) * GROW + h * 64 + dd4[it];
        kr[it] = *reinterpret_cast<const float4*>(&k[goff]);
        vr[it] = *reinterpret_cast<const float4*>(&v[goff]);
    }
#pragma unroll
    for (int it = 0; it < 2; it++) {
        float ka[4] = {kr[it].x, kr[it].y, kr[it].z, kr[it].w};
        float va[4] = {vr[it].x, vr[it].y, vr[it].z, vr[it].w};
#pragma unroll
        for (int j = 0; j < 4; j++) {
            int d = dd4[it] + j;
            *reinterpret_cast<__half*>(sm + keyl[it] * 160 + (d >> 4) * 32 + fragoff(d & 15)) =
                __float2half_rn(ka[j]);
            *reinterpret_cast<__half*>(sm + 5120 + d * 64 + (keyl[it] >> 4) * 32 + fragoff(keyl[it] & 15)) =
                __float2half_rn(va[j]);
        }
    }
    __syncthreads();
    // K: contiguous 5120B at key-half offset
    float4* dstK = g_kimg + (h * 64 + jt) * KIMG_F4 + kh * 320;
    const float4* srcK = reinterpret_cast<const float4*>(sm);
#pragma unroll
    for (int i = tid; i < 320; i += 256) dstK[i] = srcK[i];
    // V: 64B per d-row at offset kh*64 inside each 160B row
    float4* dstV = g_vimg + (h * 64 + jt) * VIMG_F4;
    const float4* srcV = reinterpret_cast<const float4*>(sm + 5120);
    {
        int d = tid >> 2, c = tid & 3;
        dstV[d * 10 + kh * 4 + c] = srcV[d * 4 + c];
    }
}

__global__ __launch_bounds__(256, 2) void zz_fa_part(
    const float* __restrict__ q)
{
    extern __shared__ char sm[];
    const uint32_t sb = smem_u32(sm);
    const int tid = threadIdx.x;
    const int w = tid >> 5, lane = tid & 31, grp = lane >> 2, qd = lane & 3;
    const int rslot = w >> 1, ch = w & 1;
    const int bx = blockIdx.x;
    const int qb = 31 - (bx >> 4);        // heavy q-tiles first
    const int h = (bx >> 1) & 7;
    const int half = bx & 1;
    const int qbase = qb * 128;

    // ---- pack Q once (scale * log2e folded in, single fp16) ----
    const float qscale = 0.125f * 1.4426950408889634f;
    for (int idx = tid; idx < 2048; idx += 256) {
        int row = idx >> 4, d4 = (idx & 15) << 2;
        float4 qv = *reinterpret_cast<const float4*>(&q[(qbase + row) * GROW + h * 64 + d4]);
        float f0 = qv.x * qscale, f1 = qv.y * qscale, f2 = qv.z * qscale, f3 = qv.w * qscale;
        __half2 h01 = __floats2half2_rn(f0, f1);
        __half2 h23 = __floats2half2_rn(f2, f3);
        uint32_t hi01 = *reinterpret_cast<uint32_t*>(&h01);
        uint32_t hi23 = *reinterpret_cast<uint32_t*>(&h23);
        int mt = row >> 4, g = row & 7, rh = (row >> 3) & 1;
        int kt = d4 >> 4, dp = d4 & 15, hf = dp >> 3, qd0 = (dp & 7) >> 1;
        int comp = hf * 2 + rh;
        char* ub = sm + QB_OFF + (mt * 8 + g) * 528 + kt * 128;
        *reinterpret_cast<uint32_t*>(ub + qd0 * 32 + comp * 4) = hi01;
        *reinterpret_cast<uint32_t*>(ub + (qd0 + 1) * 32 + comp * 4) = hi23;
    }

    float4 oacc[2][4];
    float lacc[2][2];
#pragma unroll
    for (int m = 0; m < 2; m++) {
        lacc[m][0] = 0.f; lacc[m][1] = 0.f;
#pragma unroll
        for (int j = 0; j < 4; j++) oacc[m][j] = make_float4(0.f, 0.f, 0.f, 0.f);
    }

    const int u0 = (rslot * 2) * 8 + grp;
    const int u1 = (rslot * 2 + 1) * 8 + grp;
    const int j0 = half ? (qb + 1) : 0;
    const int j1 = half ? (2 * qb + 1) : qb;

    // prologue: pair(j0) -> buf0, pair(j0+1) -> buf1 (or empty commit)
    {
        const char* gK = reinterpret_cast<const char*>(g_kimg + (h * 64 + j0) * KIMG_F4);
        const char* gV = reinterpret_cast<const char*>(g_vimg + (h * 64 + j0) * VIMG_F4);
        for (int i = tid; i < KIMG_F4; i += 256) cp16(sb + K_OFF(0) + i * 16, gK + i * 16);
        for (int i = tid; i < VIMG_F4; i += 256) cp16(sb + V_OFF(0) + i * 16, gV + i * 16);
        CP_COMMIT();
        if (j0 < j1) {
            const char* gK1 = reinterpret_cast<const char*>(g_kimg + (h * 64 + j0 + 1) * KIMG_F4);
            const char* gV1 = reinterpret_cast<const char*>(g_vimg + (h * 64 + j0 + 1) * VIMG_F4);
            for (int i = tid; i < KIMG_F4; i += 256) cp16(sb + K_OFF(1) + i * 16, gK1 + i * 16);
            for (int i = tid; i < VIMG_F4; i += 256) cp16(sb + V_OFF(1) + i * 16, gV1 + i * 16);
        }
        CP_COMMIT();
    }
    __syncthreads();   // Q pack visible

    for (int jt = j0; jt <= j1; ++jt) {
        const int b = (jt - j0) & 1;
        CP_WAIT1();        // pair(jt) landed (groups retire in commit order)
        __syncthreads();

        // ---- GEMM1: S = Q K^T (single-pass fp16) ----
        float4 sacc[2][4];
#pragma unroll
        for (int m = 0; m < 2; m++)
#pragma unroll
            for (int n = 0; n < 4; n++) sacc[m][n] = make_float4(0.f, 0.f, 0.f, 0.f);

#pragma unroll
        for (int kt = 0; kt < 4; kt++) {
            const char* qp0 = sm + QB_OFF + u0 * 528 + kt * 128 + qd * 32;
            const char* qp1 = sm + QB_OFF + u1 * 528 + kt * 128 + qd * 32;
            uint4 qh0 = *reinterpret_cast<const uint4*>(qp0);
            uint4 qh1 = *reinterpret_cast<const uint4*>(qp1);
#pragma unroll
            for (int n = 0; n < 4; n++) {
                uint2 kf = *reinterpret_cast<const uint2*>(
                    sm + K_OFF(b) + ((ch * 4 + n) * 8 + grp) * 160 + kt * 32 + qd * 8);
                mma_fp16(sacc[0][n], qh0.x, qh0.y, qh0.z, qh0.w, kf.x, kf.y);
                mma_fp16(sacc[1][n], qh1.x, qh1.y, qh1.z, qh1.w, kf.x, kf.y);
            }
        }

        // ---- exp2 (+causal mask), P store (fp16 fragments), row sums ----
        const bool domask = (jt >= 2 * qb);
#pragma unroll
        for (int m = 0; m < 2; m++) {
            float rsA = 0.f, rsB = 0.f;
            int rA = 32 * rslot + 16 * m + grp;
            int gA = qbase + rA, gB = gA + 8;
#pragma unroll
            for (int n = 0; n < 4; n++) {
                int col0 = jt * 64 + (ch * 4 + n) * 8 + 2 * qd;
                float e0, e1, e2, e3;
                if (domask) {
                    e0 = (col0     <= gA) ? exp2f(sacc[m][n].x) : 0.f;
                    e1 = (col0 + 1 <= gA) ? exp2f(sacc[m][n].y) : 0.f;
                    e2 = (col0     <= gB) ? exp2f(sacc[m][n].z) : 0.f;
                    e3 = (col0 + 1 <= gB) ? exp2f(sacc[m][n].w) : 0.f;
                } else {
                    e0 = exp2f(sacc[m][n].x); e1 = exp2f(sacc[m][n].y);
                    e2 = exp2f(sacc[m][n].z); e3 = exp2f(sacc[m][n].w);
                }
                rsA += e0 + e1; rsB += e2 + e3;
                int kc = 2 * ch + (n >> 1), nb = n & 1;
                char* pA = sm + PP_OFF + rA * 160 + kc * 32 + qd * 8 + nb * 4;
                *reinterpret_cast<__half2*>(pA) = __floats2half2_rn(e0, e1);
                *reinterpret_cast<__half2*>(pA + 8 * 160) = __floats2half2_rn(e2, e3);
            }
            rsA += __shfl_xor_sync(0xffffffffu, rsA, 1);
            rsA += __shfl_xor_sync(0xffffffffu, rsA, 2);
            rsB += __shfl_xor_sync(0xffffffffu, rsB, 1);
            rsB += __shfl_xor_sync(0xffffffffu, rsB, 2);
            if (qd == 0) {
                float* lp = reinterpret_cast<float*>(sm + LP_OFF);
                lp[ch * 128 + rA] = rsA;
                lp[ch * 128 + rA + 8] = rsB;
            }
        }
        PAIR_BAR(rslot + 1);   // P/L exchange is pair-scoped (threads [rslot*64, +64))

        // ---- GEMM2: O += P V (fp16 m16n8k16) ----
#pragma unroll
        for (int kc = 0; kc < 4; kc++) {
            const char* pa = sm + PP_OFF + (32 * rslot + grp) * 160 + kc * 32 + qd * 8;
            uint2 A0 = *reinterpret_cast<const uint2*>(pa);
            uint2 A1 = *reinterpret_cast<const uint2*>(pa + 8 * 160);
            uint2 B0 = *reinterpret_cast<const uint2*>(pa + 16 * 160);
            uint2 B1 = *reinterpret_cast<const uint2*>(pa + 24 * 160);
#pragma unroll
            for (int j = 0; j < 4; j++) {
                uint2 vf = *reinterpret_cast<const uint2*>(
                    sm + V_OFF(b) + ((ch * 4 + j) * 8 + grp) * 160 + kc * 32 + qd * 8);
                mma_fp16(oacc[0][j], A0.x, A1.x, A0.y, A1.y, vf.x, vf.y);
                mma_fp16(oacc[1][j], B0.x, B1.x, B0.y, B1.y, vf.x, vf.y);
            }
        }
        {
            const float* lp = reinterpret_cast<const float*>(sm + LP_OFF);
#pragma unroll
            for (int m = 0; m < 2; m++) {
                int rA = 32 * rslot + 16 * m + grp;
                lacc[m][0] += lp[rA] + lp[128 + rA];
                lacc[m][1] += lp[rA + 8] + lp[128 + rA + 8];
            }
        }
        __syncthreads();   // buf b fully consumed

        // prefetch pair(jt+2) into buf b (or empty commit to keep invariant)
        if (jt + 2 <= j1) {
            const char* gK = reinterpret_cast<const char*>(g_kimg + (h * 64 + jt + 2) * KIMG_F4);
            const char* gV = reinterpret_cast<const char*>(g_vimg + (h * 64 + jt + 2) * VIMG_F4);
            for (int i = tid; i < KIMG_F4; i += 256) cp16(sb + K_OFF(b) + i * 16, gK + i * 16);
            for (int i = tid; i < VIMG_F4; i += 256) cp16(sb + V_OFF(b) + i * 16, gV + i * 16);
        }
        CP_COMMIT();
    }

    // ---- write partials to scratch ----
    const int p = (h * 32 + qb) * 2 + half;
    float* Os = g_scrO + p * 8192;
#pragma unroll
    for (int m = 0; m < 2; m++) {
        int rA = 32 * rslot + 16 * m + grp, rB = rA + 8;
#pragma unroll
        for (int j = 0; j < 4; j++) {
            int db = (ch * 4 + j) * 8 + 2 * qd;
            *reinterpret_cast<float2*>(&Os[rA * 64 + db]) = make_float2(oacc[m][j].x, oacc[m][j].y);
            *reinterpret_cast<float2*>(&Os[rB * 64 + db]) = make_float2(oacc[m][j].z, oacc[m][j].w);
        }
        if (qd == 0) {
            g_scrL[p * 128 + rA] = lacc[m][0];
            g_scrL[p * 128 + rB] = lacc[m][1];
        }
    }
}

__global__ __launch_bounds__(256) void zz_fa_combine(float* __restrict__ out)
{
    __shared__ float inv_s[64];
    __shared__ float lse_s[64];
    const int b = blockIdx.x;
    const int tile = b >> 1, rh = b & 1;
    const int qt = tile >> 3, h = tile & 7;
    const int p0 = (h * 32 + qt) * 2, p1 = p0 + 1;
    const int row0 = rh * 64;
    const int t = threadIdx.x;
    if (t < 64) {
        float l = g_scrL[p0 * 128 + row0 + t] + g_scrL[p1 * 128 + row0 + t];
        inv_s[t] = 1.f / l;
        lse_s[t] = logf(l);
    }
    __syncthreads();
    const float4* A = reinterpret_cast<const float4*>(g_scrO + p0 * 8192 + row0 * 64);
    const float4* B = reinterpret_cast<const float4*>(g_scrO + p1 * 8192 + row0 * 64);
    float4 av[4], bv[4];
#pragma unroll
    for (int i = 0; i < 4; i++) { av[i] = A[t + i * 256]; bv[i] = B[t + i * 256]; }
#pragma unroll
    for (int i = 0; i < 4; i++) {
        int idx = t + i * 256;
        int row = idx >> 4, d4 = (idx & 15) << 2;
        float iv = inv_s[row];
        int sg = qt * 128 + row0 + row;
        int c = sg >> 9;
        int rk = (c < 4) ? c : 7 - c;
        int sl = (c < 4) ? (sg & 511) : 512 + (sg & 511);
        *reinterpret_cast<float4*>(&out[rk * 524288 + sl * 512 + h * 64 + d4]) =
            make_float4((av[i].x + bv[i].x) * iv, (av[i].y + bv[i].y) * iv,
                        (av[i].z + bv[i].z) * iv, (av[i].w + bv[i].w) * iv);
    }
    if (t < 64) {
        int sg = qt * 128 + row0 + t;
        int c = sg >> 9;
        int rk = (c < 4) ? c : 7 - c;
        int sl = (c < 4) ? (sg & 511) : 512 + (sg & 511);
        out[OUT_ELEMS + rk * 8192 + h * 1024 + sl] = lse_s[t];
    }
}

extern "C" void kernel_launch(void* const* d_in, const int* in_sizes, int n_in,
                              void* d_out, int out_size)
{
    const float* q = (const float*)d_in[0];
    const float* k = (const float*)d_in[1];
    const float* v = (const float*)d_in[2];
    float* out = (float*)d_out;

    cudaFuncSetAttribute(zz_fa_part, cudaFuncAttributeMaxDynamicSharedMemorySize, SMEM_TOTAL);
    dim3 pgrid(64, NH, 2);
    zz_prep<<<pgrid, 256, 9216>>>(k, v);
    zz_fa_part<<<512, 256, SMEM_TOTAL>>>(q);
    zz_fa_combine<<<512, 256>>>(out);
}

// round 13
// speedup vs baseline: 1.8129x; 1.0027x over previous
#include <cuda_runtime.h>
#include <cuda_fp16.h>
#include <math.h>
#include <stdint.h>

#define NH 8
#define GROW 512            // gmem row stride (NH*HD)
#define OUT_ELEMS 2097152   // 4*1024*8*64
#define QB_OFF 0            // Q packed fp16: 64 units * 528B
#define K_OFF(b) (33792 + (b) * 10240)   // K fp16 fragments, double-buffered
#define V_OFF(b) (54272 + (b) * 10240)   // V fp16 fragments, double-buffered
#define PP_OFF 74752        // P fp16: 128 rows * 160B
#define SMEM_TOTAL 95232
#define KIMG_F4 640         // 10240B / 16
#define VIMG_F4 640

__device__ float4 g_kimg[NH * 64 * KIMG_F4];   // packed K tile images
__device__ float4 g_vimg[NH * 64 * VIMG_F4];   // packed V tile images
__device__ float g_scrO[512 * 8192];           // partial O
__device__ float g_scrL[512 * 128];            // partial l

__device__ __forceinline__ void mma_fp16(float4& c,
    uint32_t a0, uint32_t a1, uint32_t a2, uint32_t a3, uint32_t b0, uint32_t b1)
{
    asm volatile(
        "mma.sync.aligned.m16n8k16.row.col.f32.f16.f16.f32 "
        "{%0,%1,%2,%3}, {%4,%5,%6,%7}, {%8,%9}, {%0,%1,%2,%3};\n"
        : "+f"(c.x), "+f"(c.y), "+f"(c.z), "+f"(c.w)
        : "r"(a0), "r"(a1), "r"(a2), "r"(a3), "r"(b0), "r"(b1));
}
__device__ __forceinline__ uint32_t smem_u32(const void* p) {
    uint32_t a;
    asm("{ .reg .u64 t; cvta.to.shared.u64 t, %1; cvt.u32.u64 %0, t; }" : "=r"(a) : "l"(p));
    return a;
}
__device__ __forceinline__ void cp16(uint32_t saddr, const void* g) {
    asm volatile("cp.async.cg.shared.global [%0], [%1], 16;" :: "r"(saddr), "l"(g) : "memory");
}
#define CP_COMMIT() asm volatile("cp.async.commit_group;" ::: "memory")
#define CP_WAIT1()  asm volatile("cp.async.wait_group 1;" ::: "memory")
#define PAIR_BAR(id) asm volatile("bar.sync %0, 64;" :: "r"(id) : "memory")

// fragment sub-offset of element w (0..15) inside a k16 chunk
__device__ __forceinline__ int fragoff(int w) {
    return ((w & 7) >> 1) * 8 + ((w >> 3) & 1) * 4 + (w & 1) * 2;
}

// ---- prep: pack K/V tiles into gmem fragment images (key-half per CTA) ----
__global__ __launch_bounds__(256) void zz_prep(
    const float* __restrict__ k, const float* __restrict__ v)
{
    extern __shared__ char sm[];     // [0,5120): K half-image; [5120,9216): V compact
    const int tid = threadIdx.x;
    const int jt = blockIdx.x, h = blockIdx.y, kh = blockIdx.z;
    const int kb = kh * 32;

    float4 kr[2], vr[2];
    int keyl[2], dd4[2];
#pragma unroll
    for (int it = 0; it < 2; it++) {
        int idx = tid + it * 256;
        keyl[it] = idx >> 4;
        dd4[it] = (idx & 15) << 2;
        int goff = (jt * 64 + kb + keyl[it]) * GROW + h * 64 + dd4[it];
        kr[it] = *reinterpret_cast<const float4*>(&k[goff]);
        vr[it] = *reinterpret_cast<const float4*>(&v[goff]);
    }
#pragma unroll
    for (int it = 0; it < 2; it++) {
        float ka[4] = {kr[it].x, kr[it].y, kr[it].z, kr[it].w};
        float va[4] = {vr[it].x, vr[it].y, vr[it].z, vr[it].w};
#pragma unroll
        for (int j = 0; j < 4; j++) {
            int d = dd4[it] + j;
            *reinterpret_cast<__half*>(sm + keyl[it] * 160 + (d >> 4) * 32 + fragoff(d & 15)) =
                __float2half_rn(ka[j]);
            *reinterpret_cast<__half*>(sm + 5120 + d * 64 + (keyl[it] >> 4) * 32 + fragoff(keyl[it] & 15)) =
                __float2half_rn(va[j]);
        }
    }
    __syncthreads();
    float4* dstK = g_kimg + (h * 64 + jt) * KIMG_F4 + kh * 320;
    const float4* srcK = reinterpret_cast<const float4*>(sm);
#pragma unroll
    for (int i = tid; i < 320; i += 256) dstK[i] = srcK[i];
    float4* dstV = g_vimg + (h * 64 + jt) * VIMG_F4;
    const float4* srcV = reinterpret_cast<const float4*>(sm + 5120);
    {
        int d = tid >> 2, c = tid & 3;
        dstV[d * 10 + kh * 4 + c] = srcV[d * 4 + c];
    }
}

__global__ __launch_bounds__(256, 2) void zz_fa_part(
    const float* __restrict__ q)
{
    extern __shared__ char sm[];
    const uint32_t sb = smem_u32(sm);
    const int tid = threadIdx.x;
    const int w = tid >> 5, lane = tid & 31, grp = lane >> 2, qd = lane & 3;
    const int rslot = w >> 1, ch = w & 1;
    const int bx = blockIdx.x;
    const int qb = 31 - (bx >> 4);        // heavy q-tiles first
    const int h = (bx >> 1) & 7;
    const int half = bx & 1;
    const int qbase = qb * 128;

    // ---- pack Q once (scale * log2e folded in, single fp16) ----
    const float qscale = 0.125f * 1.4426950408889634f;
    for (int idx = tid; idx < 2048; idx += 256) {
        int row = idx >> 4, d4 = (idx & 15) << 2;
        float4 qv = *reinterpret_cast<const float4*>(&q[(qbase + row) * GROW + h * 64 + d4]);
        float f0 = qv.x * qscale, f1 = qv.y * qscale, f2 = qv.z * qscale, f3 = qv.w * qscale;
        __half2 h01 = __floats2half2_rn(f0, f1);
        __half2 h23 = __floats2half2_rn(f2, f3);
        uint32_t hi01 = *reinterpret_cast<uint32_t*>(&h01);
        uint32_t hi23 = *reinterpret_cast<uint32_t*>(&h23);
        int mt = row >> 4, g = row & 7, rh = (row >> 3) & 1;
        int kt = d4 >> 4, dp = d4 & 15, hf = dp >> 3, qd0 = (dp & 7) >> 1;
        int comp = hf * 2 + rh;
        char* ub = sm + QB_OFF + (mt * 8 + g) * 528 + kt * 128;
        *reinterpret_cast<uint32_t*>(ub + qd0 * 32 + comp * 4) = hi01;
        *reinterpret_cast<uint32_t*>(ub + (qd0 + 1) * 32 + comp * 4) = hi23;
    }

    float4 oacc[2][4];
    float4 lacc4[2];
#pragma unroll
    for (int m = 0; m < 2; m++) {
        lacc4[m] = make_float4(0.f, 0.f, 0.f, 0.f);
#pragma unroll
        for (int j = 0; j < 4; j++) oacc[m][j] = make_float4(0.f, 0.f, 0.f, 0.f);
    }

    const int u0 = (rslot * 2) * 8 + grp;
    const int u1 = (rslot * 2 + 1) * 8 + grp;
    const int j0 = half ? (qb + 1) : 0;
    const int j1 = half ? (2 * qb + 1) : qb;
    const uint32_t ONES2 = 0x3C003C00u;   // half2 {1.0, 1.0}

    // prologue: pair(j0) -> buf0, pair(j0+1) -> buf1 (or empty commit)
    {
        const char* gK = reinterpret_cast<const char*>(g_kimg + (h * 64 + j0) * KIMG_F4);
        const char* gV = reinterpret_cast<const char*>(g_vimg + (h * 64 + j0) * VIMG_F4);
        for (int i = tid; i < KIMG_F4; i += 256) cp16(sb + K_OFF(0) + i * 16, gK + i * 16);
        for (int i = tid; i < VIMG_F4; i += 256) cp16(sb + V_OFF(0) + i * 16, gV + i * 16);
        CP_COMMIT();
        if (j0 < j1) {
            const char* gK1 = reinterpret_cast<const char*>(g_kimg + (h * 64 + j0 + 1) * KIMG_F4);
            const char* gV1 = reinterpret_cast<const char*>(g_vimg + (h * 64 + j0 + 1) * VIMG_F4);
            for (int i = tid; i < KIMG_F4; i += 256) cp16(sb + K_OFF(1) + i * 16, gK1 + i * 16);
            for (int i = tid; i < VIMG_F4; i += 256) cp16(sb + V_OFF(1) + i * 16, gV1 + i * 16);
        }
        CP_COMMIT();
    }
    __syncthreads();   // Q pack visible

    for (int jt = j0; jt <= j1; ++jt) {
        const int b = (jt - j0) & 1;
        CP_WAIT1();        // pair(jt) landed (groups retire in commit order)
        __syncthreads();

        // ---- GEMM1: S = Q K^T (single-pass fp16) ----
        float4 sacc[2][4];
#pragma unroll
        for (int m = 0; m < 2; m++)
#pragma unroll
            for (int n = 0; n < 4; n++) sacc[m][n] = make_float4(0.f, 0.f, 0.f, 0.f);

#pragma unroll
        for (int kt = 0; kt < 4; kt++) {
            const char* qp0 = sm + QB_OFF + u0 * 528 + kt * 128 + qd * 32;
            const char* qp1 = sm + QB_OFF + u1 * 528 + kt * 128 + qd * 32;
            uint4 qh0 = *reinterpret_cast<const uint4*>(qp0);
            uint4 qh1 = *reinterpret_cast<const uint4*>(qp1);
#pragma unroll
            for (int n = 0; n < 4; n++) {
                uint2 kf = *reinterpret_cast<const uint2*>(
                    sm + K_OFF(b) + ((ch * 4 + n) * 8 + grp) * 160 + kt * 32 + qd * 8);
                mma_fp16(sacc[0][n], qh0.x, qh0.y, qh0.z, qh0.w, kf.x, kf.y);
                mma_fp16(sacc[1][n], qh1.x, qh1.y, qh1.z, qh1.w, kf.x, kf.y);
            }
        }

        // ---- exp2 via half2 MUFU (+causal mask), P store (fp16 fragments) ----
        const bool domask = (jt >= 2 * qb);
#pragma unroll
        for (int m = 0; m < 2; m++) {
            int rA = 32 * rslot + 16 * m + grp;
            int gA = qbase + rA, gB = gA + 8;
#pragma unroll
            for (int n = 0; n < 4; n++) {
                float sx = sacc[m][n].x, sy = sacc[m][n].y;
                float sz = sacc[m][n].z, sw = sacc[m][n].w;
                if (domask) {
                    int col0 = jt * 64 + (ch * 4 + n) * 8 + 2 * qd;
                    if (col0     > gA) sx = -60000.f;
                    if (col0 + 1 > gA) sy = -60000.f;
                    if (col0     > gB) sz = -60000.f;
                    if (col0 + 1 > gB) sw = -60000.f;
                }
                __half2 e01 = h2exp2(__floats2half2_rn(sx, sy));
                __half2 e23 = h2exp2(__floats2half2_rn(sz, sw));
                int kc = 2 * ch + (n >> 1), nb = n & 1;
                char* pA = sm + PP_OFF + rA * 160 + kc * 32 + qd * 8 + nb * 4;
                *reinterpret_cast<__half2*>(pA) = e01;
                *reinterpret_cast<__half2*>(pA + 8 * 160) = e23;
            }
        }
        PAIR_BAR(rslot + 1);   // P exchange is pair-scoped (threads [rslot*64, +64))

        // ---- GEMM2: O += P V, l += P·1 (fp16 m16n8k16) ----
#pragma unroll
        for (int kc = 0; kc < 4; kc++) {
            const char* pa = sm + PP_OFF + (32 * rslot + grp) * 160 + kc * 32 + qd * 8;
            uint2 A0 = *reinterpret_cast<const uint2*>(pa);
            uint2 A1 = *reinterpret_cast<const uint2*>(pa + 8 * 160);
            uint2 B0 = *reinterpret_cast<const uint2*>(pa + 16 * 160);
            uint2 B1 = *reinterpret_cast<const uint2*>(pa + 24 * 160);
#pragma unroll
            for (int j = 0; j < 4; j++) {
                uint2 vf = *reinterpret_cast<const uint2*>(
                    sm + V_OFF(b) + ((ch * 4 + j) * 8 + grp) * 160 + kc * 32 + qd * 8);
                mma_fp16(oacc[0][j], A0.x, A1.x, A0.y, A1.y, vf.x, vf.y);
                mma_fp16(oacc[1][j], B0.x, B1.x, B0.y, B1.y, vf.x, vf.y);
            }
            mma_fp16(lacc4[0], A0.x, A1.x, A0.y, A1.y, ONES2, ONES2);
            mma_fp16(lacc4[1], B0.x, B1.x, B0.y, B1.y, ONES2, ONES2);
        }
        __syncthreads();   // buf b + P fully consumed

        // prefetch pair(jt+2) into buf b (or empty commit to keep invariant)
        if (jt + 2 <= j1) {
            const char* gK = reinterpret_cast<const char*>(g_kimg + (h * 64 + jt + 2) * KIMG_F4);
            const char* gV = reinterpret_cast<const char*>(g_vimg + (h * 64 + jt + 2) * VIMG_F4);
            for (int i = tid; i < KIMG_F4; i += 256) cp16(sb + K_OFF(b) + i * 16, gK + i * 16);
            for (int i = tid; i < VIMG_F4; i += 256) cp16(sb + V_OFF(b) + i * 16, gV + i * 16);
        }
        CP_COMMIT();
    }

    // ---- write partials to scratch ----
    const int p = (h * 32 + qb) * 2 + half;
    float* Os = g_scrO + p * 8192;
#pragma unroll
    for (int m = 0; m < 2; m++) {
        int rA = 32 * rslot + 16 * m + grp, rB = rA + 8;
#pragma unroll
        for (int j = 0; j < 4; j++) {
            int db = (ch * 4 + j) * 8 + 2 * qd;
            *reinterpret_cast<float2*>(&Os[rA * 64 + db]) = make_float2(oacc[m][j].x, oacc[m][j].y);
            *reinterpret_cast<float2*>(&Os[rB * 64 + db]) = make_float2(oacc[m][j].z, oacc[m][j].w);
        }
        if (qd == 0) {
            g_scrL[p * 128 + rA] = lacc4[m].x;   // row rA sum (all n cols identical)
            g_scrL[p * 128 + rB] = lacc4[m].z;   // row rB sum
        }
    }
}

__global__ __launch_bounds__(256) void zz_fa_combine(float* __restrict__ out)
{
    __shared__ float inv_s[64];
    __shared__ float lse_s[64];
    const int b = blockIdx.x;
    const int tile = b >> 1, rh = b & 1;
    const int qt = tile >> 3, h = tile & 7;
    const int p0 = (h * 32 + qt) * 2, p1 = p0 + 1;
    const int row0 = rh * 64;
    const int t = threadIdx.x;
    if (t < 64) {
        float l = g_scrL[p0 * 128 + row0 + t] + g_scrL[p1 * 128 + row0 + t];
        inv_s[t] = 1.f / l;
        lse_s[t] = logf(l);
    }
    __syncthreads();
    const float4* A = reinterpret_cast<const float4*>(g_scrO + p0 * 8192 + row0 * 64);
    const float4* B = reinterpret_cast<const float4*>(g_scrO + p1 * 8192 + row0 * 64);
    float4 av[4], bv[4];
#pragma unroll
    for (int i = 0; i < 4; i++) { av[i] = A[t + i * 256]; bv[i] = B[t + i * 256]; }
#pragma unroll
    for (int i = 0; i < 4; i++) {
        int idx = t + i * 256;
        int row = idx >> 4, d4 = (idx & 15) << 2;
        float iv = inv_s[row];
        int sg = qt * 128 + row0 + row;
        int c = sg >> 9;
        int rk = (c < 4) ? c : 7 - c;
        int sl = (c < 4) ? (sg & 511) : 512 + (sg & 511);
        *reinterpret_cast<float4*>(&out[rk * 524288 + sl * 512 + h * 64 + d4]) =
            make_float4((av[i].x + bv[i].x) * iv, (av[i].y + bv[i].y) * iv,
                        (av[i].z + bv[i].z) * iv, (av[i].w + bv[i].w) * iv);
    }
    if (t < 64) {
        int sg = qt * 128 + row0 + t;
        int c = sg >> 9;
        int rk = (c < 4) ? c : 7 - c;
        int sl = (c < 4) ? (sg & 511) : 512 + (sg & 511);
        out[OUT_ELEMS + rk * 8192 + h * 1024 + sl] = lse_s[t];
    }
}

extern "C" void kernel_launch(void* const* d_in, const int* in_sizes, int n_in,
                              void* d_out, int out_size)
{
    const float* q = (const float*)d_in[0];
    const float* k = (const float*)d_in[1];
    const float* v = (const float*)d_in[2];
    float* out = (float*)d_out;

    cudaFuncSetAttribute(zz_fa_part, cudaFuncAttributeMaxDynamicSharedMemorySize, SMEM_TOTAL);
    dim3 pgrid(64, NH, 2);
    zz_prep<<<pgrid, 256, 9216>>>(k, v);
    zz_fa_part<<<512, 256, SMEM_TOTAL>>>(q);
    zz_fa_combine<<<512, 256>>>(out);
}

// round 14
// speedup vs baseline: 1.9068x; 1.0518x over previous
#include <cuda_runtime.h>
#include <cuda_fp16.h>
#include <math.h>
#include <stdint.h>

#define NH 8
#define GROW 512            // gmem row stride (NH*HD)
#define OUT_ELEMS 2097152   // 4*1024*8*64
#define QB_OFF 0            // Q fragment image: 16384B
#define K_OFF(b) (16384 + (b) * 8192)    // K fragment image, double-buffered
#define V_OFF(b) (32768 + (b) * 8192)    // V fragment image, double-buffered
#define PP_OFF 49152        // P: [rslot4][kc4][grp8*144B] = 18432B
#define SMEM_TOTAL 67584
#define KIMG_F4 512         // 8192B / 16
#define VIMG_F4 512

__device__ float4 g_kimg[NH * 64 * KIMG_F4];   // packed K tile images
__device__ float4 g_vimg[NH * 64 * VIMG_F4];   // packed V tile images
__device__ float g_scrO[512 * 8192];           // partial O
__device__ float g_scrL[512 * 128];            // partial l

__device__ __forceinline__ void mma_fp16(float4& c,
    uint32_t a0, uint32_t a1, uint32_t a2, uint32_t a3, uint32_t b0, uint32_t b1)
{
    asm volatile(
        "mma.sync.aligned.m16n8k16.row.col.f32.f16.f16.f32 "
        "{%0,%1,%2,%3}, {%4,%5,%6,%7}, {%8,%9}, {%0,%1,%2,%3};\n"
        : "+f"(c.x), "+f"(c.y), "+f"(c.z), "+f"(c.w)
        : "r"(a0), "r"(a1), "r"(a2), "r"(a3), "r"(b0), "r"(b1));
}
__device__ __forceinline__ uint32_t smem_u32(const void* p) {
    uint32_t a;
    asm("{ .reg .u64 t; cvta.to.shared.u64 t, %1; cvt.u32.u64 %0, t; }" : "=r"(a) : "l"(p));
    return a;
}
__device__ __forceinline__ void cp16(uint32_t saddr, const void* g) {
    asm volatile("cp.async.cg.shared.global [%0], [%1], 16;" :: "r"(saddr), "l"(g) : "memory");
}
#define CP_COMMIT() asm volatile("cp.async.commit_group;" ::: "memory")
#define CP_WAIT1()  asm volatile("cp.async.wait_group 1;" ::: "memory")
#define PAIR_BAR(id) asm volatile("bar.sync %0, 64;" :: "r"(id) : "memory")

__device__ __forceinline__ uint32_t h2u(__half2 h) { return *reinterpret_cast<uint32_t*>(&h); }

// ---- prep: pack K/V tiles into gmem fragment images (key-half per CTA) ----
// K image layout (8192B/tile): addr = ((kt*4 + (key>>4))*32 + (key&7)*4 + ((d&7)>>1))*16
//                                   + ((key>>3)&1)*8 + ((d>>3)&1)*4 + (d&1)*2
// V image layout (8192B/tile): addr = (((key>>4)*4 + (d>>4))*32 + (d&7)*4 + ((key&7)>>1))*16
//                                   + ((d>>3)&1)*8 + ((key>>3)&1)*4 + (key&1)*2
__global__ __launch_bounds__(256) void zz_prep(
    const float* __restrict__ k, const float* __restrict__ v)
{
    __shared__ char sm[8192];   // [0,4096): K half-image; [4096,8192): V half-image
    const int tid = threadIdx.x;
    const int jt = blockIdx.x, h = blockIdx.y, kh = blockIdx.z;
    const int kb = kh * 32;

    float4 kr[2], vr[2];
    int keyl[2], dd4[2];
#pragma unroll
    for (int it = 0; it < 2; it++) {
        int idx = tid + it * 256;
        keyl[it] = idx >> 4;            // 0..31
        dd4[it] = (idx & 15) << 2;
        int goff = (jt * 64 + kb + keyl[it]) * GROW + h * 64 + dd4[it];
        kr[it] = *reinterpret_cast<const float4*>(&k[goff]);
        vr[it] = *reinterpret_cast<const float4*>(&v[goff]);
    }
#pragma unroll
    for (int it = 0; it < 2; it++) {
        float ka[4] = {kr[it].x, kr[it].y, kr[it].z, kr[it].w};
        float va[4] = {vr[it].x, vr[it].y, vr[it].z, vr[it].w};
        int kl = keyl[it];
#pragma unroll
        for (int j = 0; j < 4; j++) {
            int d = dd4[it] + j;
            // K half-image: local gp = kl>>4, kt stride 1024
            int kaddr = (d >> 4) * 1024 + (kl >> 4) * 512 + (kl & 7) * 64
                      + ((d & 7) >> 1) * 16 + ((kl >> 3) & 1) * 8 + ((d >> 3) & 1) * 4 + (d & 1) * 2;
            *reinterpret_cast<__half*>(sm + kaddr) = __float2half_rn(ka[j]);
            // V half-image: local kc = kl>>4, stride 2048
            int vaddr = 4096 + (kl >> 4) * 2048 + (d >> 4) * 512 + (d & 7) * 64
                      + ((kl & 7) >> 1) * 16 + ((d >> 3) & 1) * 8 + ((kl >> 3) & 1) * 4 + (kl & 1) * 2;
            *reinterpret_cast<__half*>(sm + vaddr) = __float2half_rn(va[j]);
        }
    }
    __syncthreads();
    // K: per kt, our half occupies f4 [kt*128 + kh*64, +64)
    {
        const float4* srcK = reinterpret_cast<const float4*>(sm);
        float4* dstK = g_kimg + (h * 64 + jt) * KIMG_F4;
        int ktc = tid >> 6, within = tid & 63;
        dstK[ktc * 128 + kh * 64 + within] = srcK[tid];
    }
    // V: contiguous 4096B at kh*4096
    {
        const float4* srcV = reinterpret_cast<const float4*>(sm + 4096);
        float4* dstV = g_vimg + (h * 64 + jt) * VIMG_F4;
        dstV[kh * 256 + tid] = srcV[tid];
    }
}

__global__ __launch_bounds__(256, 2) void zz_fa_part(
    const float* __restrict__ q)
{
    extern __shared__ char sm[];
    const uint32_t sb = smem_u32(sm);
    const int tid = threadIdx.x;
    const int w = tid >> 5, lane = tid & 31, grp = lane >> 2, qd = lane & 3;
    const int rslot = w >> 1, ch = w & 1;
    const int bx = blockIdx.x;
    const int qb = 31 - (bx >> 4);        // heavy q-tiles first
    const int h = (bx >> 1) & 7;
    const int half = bx & 1;
    const int qbase = qb * 128;

    // ---- pack Q once (scale * log2e folded in) into fragment image ----
    const float qscale = 0.125f * 1.4426950408889634f;
    for (int idx = tid; idx < 2048; idx += 256) {
        int row = idx >> 4, d4 = (idx & 15) << 2;
        float4 qv = *reinterpret_cast<const float4*>(&q[(qbase + row) * GROW + h * 64 + d4]);
        __half2 h01 = __floats2half2_rn(qv.x * qscale, qv.y * qscale);
        __half2 h23 = __floats2half2_rn(qv.z * qscale, qv.w * qscale);
        int mtile = row >> 4, g = row & 7, rh = (row >> 3) & 1;
        int kt = d4 >> 4, qdq = (d4 & 7) >> 1, hi = (d4 >> 3) & 1;
        int base = QB_OFF + ((mtile * 4 + kt) * 32 + g * 4 + qdq) * 16 + hi * 8 + rh * 4;
        *reinterpret_cast<__half2*>(sm + base) = h01;
        *reinterpret_cast<__half2*>(sm + base + 16) = h23;
    }

    float4 oacc[2][4];
    float4 lacc4[2];
#pragma unroll
    for (int m = 0; m < 2; m++) {
        lacc4[m] = make_float4(0.f, 0.f, 0.f, 0.f);
#pragma unroll
        for (int j = 0; j < 4; j++) oacc[m][j] = make_float4(0.f, 0.f, 0.f, 0.f);
    }

    const int mt0 = 2 * rslot, mt1 = 2 * rslot + 1;
    const int j0 = half ? (qb + 1) : 0;
    const int j1 = half ? (2 * qb + 1) : qb;
    const uint32_t ONES2 = 0x3C003C00u;   // half2 {1.0, 1.0}

    // prologue: pair(j0) -> buf0, pair(j0+1) -> buf1 (or empty commit)
    {
        const char* gK = reinterpret_cast<const char*>(g_kimg + (h * 64 + j0) * KIMG_F4);
        const char* gV = reinterpret_cast<const char*>(g_vimg + (h * 64 + j0) * VIMG_F4);
        for (int i = tid; i < KIMG_F4; i += 256) cp16(sb + K_OFF(0) + i * 16, gK + i * 16);
        for (int i = tid; i < VIMG_F4; i += 256) cp16(sb + V_OFF(0) + i * 16, gV + i * 16);
        CP_COMMIT();
        if (j0 < j1) {
            const char* gK1 = reinterpret_cast<const char*>(g_kimg + (h * 64 + j0 + 1) * KIMG_F4);
            const char* gV1 = reinterpret_cast<const char*>(g_vimg + (h * 64 + j0 + 1) * VIMG_F4);
            for (int i = tid; i < KIMG_F4; i += 256) cp16(sb + K_OFF(1) + i * 16, gK1 + i * 16);
            for (int i = tid; i < VIMG_F4; i += 256) cp16(sb + V_OFF(1) + i * 16, gV1 + i * 16);
        }
        CP_COMMIT();
    }
    __syncthreads();   // Q pack visible

    for (int jt = j0; jt <= j1; ++jt) {
        const int b = (jt - j0) & 1;
        CP_WAIT1();        // pair(jt) landed (groups retire in commit order)
        __syncthreads();

        // ---- GEMM1: S = Q K^T (fp16), LDS.128 feeds 2 MMAs ----
        float4 sacc[2][4];
#pragma unroll
        for (int m = 0; m < 2; m++)
#pragma unroll
            for (int n = 0; n < 4; n++) sacc[m][n] = make_float4(0.f, 0.f, 0.f, 0.f);

#pragma unroll
        for (int kt = 0; kt < 4; kt++) {
            uint4 qh0 = *reinterpret_cast<const uint4*>(
                sm + QB_OFF + ((mt0 * 4 + kt) * 32 + grp * 4 + qd) * 16);
            uint4 qh1 = *reinterpret_cast<const uint4*>(
                sm + QB_OFF + ((mt1 * 4 + kt) * 32 + grp * 4 + qd) * 16);
#pragma unroll
            for (int np = 0; np < 2; np++) {
                int gp = ch * 2 + np;
                uint4 kk = *reinterpret_cast<const uint4*>(
                    sm + K_OFF(b) + ((kt * 4 + gp) * 32 + grp * 4 + qd) * 16);
                mma_fp16(sacc[0][2 * np],     qh0.x, qh0.y, qh0.z, qh0.w, kk.x, kk.y);
                mma_fp16(sacc[0][2 * np + 1], qh0.x, qh0.y, qh0.z, qh0.w, kk.z, kk.w);
                mma_fp16(sacc[1][2 * np],     qh1.x, qh1.y, qh1.z, qh1.w, kk.x, kk.y);
                mma_fp16(sacc[1][2 * np + 1], qh1.x, qh1.y, qh1.z, qh1.w, kk.z, kk.w);
            }
        }

        // ---- exp2 via half2 MUFU (+causal mask), P store (uint2 units) ----
        const bool domask = (jt >= 2 * qb);
#pragma unroll
        for (int m = 0; m < 2; m++) {
            int rA = 32 * rslot + 16 * m + grp;
            int gA = qbase + rA, gB = gA + 8;
#pragma unroll
            for (int np = 0; np < 2; np++) {
                float4 s0 = sacc[m][2 * np];       // keys c, c+1
                float4 s1 = sacc[m][2 * np + 1];   // keys c+8, c+9
                if (domask) {
                    int c = jt * 64 + (2 * ch + np) * 16 + 2 * qd;
                    if (c     > gA) s0.x = -60000.f;
                    if (c + 1 > gA) s0.y = -60000.f;
                    if (c     > gB) s0.z = -60000.f;
                    if (c + 1 > gB) s0.w = -60000.f;
                    if (c + 8 > gA) s1.x = -60000.f;
                    if (c + 9 > gA) s1.y = -60000.f;
                    if (c + 8 > gB) s1.z = -60000.f;
                    if (c + 9 > gB) s1.w = -60000.f;
                }
                uint32_t eA0 = h2u(h2exp2(__floats2half2_rn(s0.x, s0.y)));
                uint32_t eA1 = h2u(h2exp2(__floats2half2_rn(s1.x, s1.y)));
                uint32_t eB0 = h2u(h2exp2(__floats2half2_rn(s0.z, s0.w)));
                uint32_t eB1 = h2u(h2exp2(__floats2half2_rn(s1.z, s1.w)));
                char* pb = sm + PP_OFF + (rslot * 4 + 2 * ch + np) * 1152 + grp * 144 + qd * 32;
                *reinterpret_cast<uint2*>(pb + (2 * m) * 8)     = make_uint2(eA0, eA1);
                *reinterpret_cast<uint2*>(pb + (2 * m + 1) * 8) = make_uint2(eB0, eB1);
            }
        }
        PAIR_BAR(rslot + 1);   // P exchange is pair-scoped (threads [rslot*64, +64))

        // ---- GEMM2: O += P V, l += P·1 ----
#pragma unroll
        for (int kc = 0; kc < 4; kc++) {
            const char* pbase = sm + PP_OFF + (rslot * 4 + kc) * 1152 + grp * 144 + qd * 32;
            uint4 Pa = *reinterpret_cast<const uint4*>(pbase);        // m=0: {rA unit, rB unit}
            uint4 Pb = *reinterpret_cast<const uint4*>(pbase + 16);   // m=1
#pragma unroll
            for (int np = 0; np < 2; np++) {
                int gp = ch * 2 + np;
                uint4 vv = *reinterpret_cast<const uint4*>(
                    sm + V_OFF(b) + ((kc * 4 + gp) * 32 + grp * 4 + qd) * 16);
                mma_fp16(oacc[0][2 * np],     Pa.x, Pa.z, Pa.y, Pa.w, vv.x, vv.y);
                mma_fp16(oacc[0][2 * np + 1], Pa.x, Pa.z, Pa.y, Pa.w, vv.z, vv.w);
                mma_fp16(oacc[1][2 * np],     Pb.x, Pb.z, Pb.y, Pb.w, vv.x, vv.y);
                mma_fp16(oacc[1][2 * np + 1], Pb.x, Pb.z, Pb.y, Pb.w, vv.z, vv.w);
            }
            mma_fp16(lacc4[0], Pa.x, Pa.z, Pa.y, Pa.w, ONES2, ONES2);
            mma_fp16(lacc4[1], Pb.x, Pb.z, Pb.y, Pb.w, ONES2, ONES2);
        }
        __syncthreads();   // buf b + P fully consumed

        // prefetch pair(jt+2) into buf b (or empty commit to keep invariant)
        if (jt + 2 <= j1) {
            const char* gK = reinterpret_cast<const char*>(g_kimg + (h * 64 + jt + 2) * KIMG_F4);
            const char* gV = reinterpret_cast<const char*>(g_vimg + (h * 64 + jt + 2) * VIMG_F4);
            for (int i = tid; i < KIMG_F4; i += 256) cp16(sb + K_OFF(b) + i * 16, gK + i * 16);
            for (int i = tid; i < VIMG_F4; i += 256) cp16(sb + V_OFF(b) + i * 16, gV + i * 16);
        }
        CP_COMMIT();
    }

    // ---- write partials to scratch ----
    const int p = (h * 32 + qb) * 2 + half;
    float* Os = g_scrO + p * 8192;
#pragma unroll
    for (int m = 0; m < 2; m++) {
        int rA = 32 * rslot + 16 * m + grp, rB = rA + 8;
#pragma unroll
        for (int j = 0; j < 4; j++) {
            int db = (ch * 4 + j) * 8 + 2 * qd;
            *reinterpret_cast<float2*>(&Os[rA * 64 + db]) = make_float2(oacc[m][j].x, oacc[m][j].y);
            *reinterpret_cast<float2*>(&Os[rB * 64 + db]) = make_float2(oacc[m][j].z, oacc[m][j].w);
        }
        if (qd == 0) {
            g_scrL[p * 128 + rA] = lacc4[m].x;
            g_scrL[p * 128 + rB] = lacc4[m].z;
        }
    }
}

__global__ __launch_bounds__(256) void zz_fa_combine(float* __restrict__ out)
{
    __shared__ float inv_s[64];
    __shared__ float lse_s[64];
    const int b = blockIdx.x;
    const int tile = b >> 1, rh = b & 1;
    const int qt = tile >> 3, h = tile & 7;
    const int p0 = (h * 32 + qt) * 2, p1 = p0 + 1;
    const int row0 = rh * 64;
    const int t = threadIdx.x;
    if (t < 64) {
        float l = g_scrL[p0 * 128 + row0 + t] + g_scrL[p1 * 128 + row0 + t];
        inv_s[t] = 1.f / l;
        lse_s[t] = logf(l);
    }
    __syncthreads();
    const float4* A = reinterpret_cast<const float4*>(g_scrO + p0 * 8192 + row0 * 64);
    const float4* B = reinterpret_cast<const float4*>(g_scrO + p1 * 8192 + row0 * 64);
    float4 av[4], bv[4];
#pragma unroll
    for (int i = 0; i < 4; i++) { av[i] = A[t + i * 256]; bv[i] = B[t + i * 256]; }
#pragma unroll
    for (int i = 0; i < 4; i++) {
        int idx = t + i * 256;
        int row = idx >> 4, d4 = (idx & 15) << 2;
        float iv = inv_s[row];
        int sg = qt * 128 + row0 + row;
        int c = sg >> 9;
        int rk = (c < 4) ? c : 7 - c;
        int sl = (c < 4) ? (sg & 511) : 512 + (sg & 511);
        *reinterpret_cast<float4*>(&out[rk * 524288 + sl * 512 + h * 64 + d4]) =
            make_float4((av[i].x + bv[i].x) * iv, (av[i].y + bv[i].y) * iv,
                        (av[i].z + bv[i].z) * iv, (av[i].w + bv[i].w) * iv);
    }
    if (t < 64) {
        int sg = qt * 128 + row0 + t;
        int c = sg >> 9;
        int rk = (c < 4) ? c : 7 - c;
        int sl = (c < 4) ? (sg & 511) : 512 + (sg & 511);
        out[OUT_ELEMS + rk * 8192 + h * 1024 + sl] = lse_s[t];
    }
}

extern "C" void kernel_launch(void* const* d_in, const int* in_sizes, int n_in,
                              void* d_out, int out_size)
{
    const float* q = (const float*)d_in[0];
    const float* k = (const float*)d_in[1];
    const float* v = (const float*)d_in[2];
    float* out = (float*)d_out;

    cudaFuncSetAttribute(zz_fa_part, cudaFuncAttributeMaxDynamicSharedMemorySize, SMEM_TOTAL);
    dim3 pgrid(64, NH, 2);
    zz_prep<<<pgrid, 256>>>(k, v);
    zz_fa_part<<<512, 256, SMEM_TOTAL>>>(q);
    zz_fa_combine<<<512, 256>>>(out);
}